// round 9
// baseline (speedup 1.0000x reference)
#include <cuda_runtime.h>
#include <math.h>

#define BB 4
#define NN 4096
#define RR 32
#define VV (RR*RR*RR)

__device__ float g_grid[BB*VV*64];
__device__ float g_cnt[BB*VV];
__device__ float g_nc[BB*3*NN];
__device__ float g_x[BB*VV*64];
__device__ float g_wt[9*3*64*64];
__device__ float g_semean[BB*64];
__device__ float g_se[BB*64];
__device__ float g_px[BB*NN*64];
__device__ float g_pq[BB*NN*16];
__device__ float g_pk[BB*NN*16];
__device__ float g_pv[BB*NN*64];
__device__ float g_pop[4*BB*NN*64];
__device__ float g_po[BB*NN*64];
__device__ float g_pmx[4*BB*NN];
__device__ float g_pss[4*BB*NN];

typedef unsigned long long ull;

__device__ __forceinline__ ull pack2(float x, float y) {
    ull r; asm("mov.b64 %0, {%1, %2};" : "=l"(r) : "f"(x), "f"(y)); return r;
}
__device__ __forceinline__ float2 unpack2(ull v) {
    float2 f; asm("mov.b64 {%0, %1}, %2;" : "=f"(f.x), "=f"(f.y) : "l"(v)); return f;
}
__device__ __forceinline__ void fma2(ull &d, ull a, ull b) {
    asm("fma.rn.f32x2 %0, %1, %2, %0;" : "+l"(d) : "l"(a), "l"(b));
}
__device__ __forceinline__ void mul2(ull &d, ull a) {
    asm("mul.rn.f32x2 %0, %0, %1;" : "+l"(d) : "l"(a));
}
// weight-row swizzle: injects all 4 q-bits into the 8B-group index
__device__ __forceinline__ int wswz(int row) {
    return (row & 12) | ((row & 3) ^ ((row >> 4) & 3));
}

#define WS 66

// stage a 64x64 row-major weight matrix into swizzled stride-64 smem
#define STAGE_W(WN, SRCROW) \
    for (int i_=threadIdx.x; i_<4096; i_+=256){ \
        int jj_=i_>>6, ci_=i_&63; \
        (WN)[jj_*64 + 2*((ci_>>1) ^ wswz(jj_)) + (ci_&1)] = (SRCROW); \
    }

// ci-pair GEMM: ACC[i][j] (f32x2 partial sums over even/odd ci)
// ABUF rows (r*4+i) stride WS; WN swizzled stride-64
#define GEMM_P(ACC, ABUF, WN) \
    { int e_ = q>>2; \
      int sw0_=(q&3)*4+(0^e_), sw1_=(q&3)*4+(1^e_), sw2_=(q&3)*4+(2^e_), sw3_=(q&3)*4+(3^e_); \
      int rb0_=(q*4+0)*64, rb1_=(q*4+1)*64, rb2_=(q*4+2)*64, rb3_=(q*4+3)*64; \
      for (int cp_=0; cp_<32; cp_++) { \
        ull w0_ = *(const ull*)&(WN)[rb0_ + 2*(cp_ ^ sw0_)]; \
        ull w1_ = *(const ull*)&(WN)[rb1_ + 2*(cp_ ^ sw1_)]; \
        ull w2_ = *(const ull*)&(WN)[rb2_ + 2*(cp_ ^ sw2_)]; \
        ull w3_ = *(const ull*)&(WN)[rb3_ + 2*(cp_ ^ sw3_)]; \
        _Pragma("unroll") \
        for (int i_=0;i_<4;i_++){ \
            ull a_ = *(const ull*)&(ABUF)[(r*4+i_)*WS + 2*cp_]; \
            fma2(ACC[i_][0], a_, w0_); fma2(ACC[i_][1], a_, w1_); \
            fma2(ACC[i_][2], a_, w2_); fma2(ACC[i_][3], a_, w3_); \
        } } }

// fused init (zero + conv weight transpose) + per-batch coord stats
__global__ void k_initstats(const float* __restrict__ w, const float* __restrict__ coords) {
    int blk = blockIdx.x;
    int t = threadIdx.x;
    if (blk < 8192) {
        int i = blk*256 + t;
        if (i < BB*VV*64/4) ((float4*)g_grid)[i] = make_float4(0.f,0.f,0.f,0.f);
        if (i < BB*VV)      g_cnt[i] = 0.f;
        if (i < BB*64)      g_semean[i] = 0.f;
        if (i < 9*3*64*64) {
            int co = i & 63;
            int ci = (i>>6) & 63;
            int kz = (i>>12) % 3;
            int g  = i / 12288;
            int dx = g/3, dy = g%3;
            g_wt[i] = w[(((co*64+ci)*3+dx)*3+dy)*3 + kz];
        }
        return;
    }
    int b = blk - 8192;
    __shared__ float red[256];
    __shared__ float mS[3], mxS;
    const float* cb = coords + b*3*NN;
    float s0=0.f, s1=0.f, s2=0.f;
    for (int n=t; n<NN; n+=256) { s0+=cb[n]; s1+=cb[NN+n]; s2+=cb[2*NN+n]; }
    float sv[3] = {s0,s1,s2};
    for (int d=0; d<3; d++) {
        red[t]=sv[d]; __syncthreads();
        for (int o=128;o;o>>=1){ if(t<o) red[t]+=red[t+o]; __syncthreads(); }
        if (t==0) mS[d] = red[0]*(1.f/NN);
        __syncthreads();
    }
    float m0=mS[0], m1=mS[1], m2=mS[2];
    float mx = 0.f;
    for (int n=t; n<NN; n+=256) {
        float dx=cb[n]-m0, dy=cb[NN+n]-m1, dz=cb[2*NN+n]-m2;
        mx = fmaxf(mx, dx*dx+dy*dy+dz*dz);
    }
    red[t]=mx; __syncthreads();
    for (int o=128;o;o>>=1){ if(t<o) red[t]=fmaxf(red[t],red[t+o]); __syncthreads(); }
    if (t==0) mxS = sqrtf(red[0]);
    __syncthreads();
    float inv = 1.f/(2.f*mxS);
    float* ncb = g_nc + b*3*NN;
    for (int n=t; n<NN; n+=256) {
        float v0 = ((cb[n]      -m0)*inv + 0.5f)*RR;
        float v1 = ((cb[NN+n]   -m1)*inv + 0.5f)*RR;
        float v2 = ((cb[2*NN+n] -m2)*inv + 0.5f)*RR;
        ncb[n]      = fminf(fmaxf(v0,0.f), 31.f);
        ncb[NN+n]   = fminf(fmaxf(v1,0.f), 31.f);
        ncb[2*NN+n] = fminf(fmaxf(v2,0.f), 31.f);
    }
}

__global__ void k_scatter(const float* __restrict__ feat) {
    int i = blockIdx.x*256 + threadIdx.x;
    const int PN = BB*NN;
    if (i >= 64*PN) return;
    int c = i / PN;
    int r = i % PN;
    int b = r / NN, n = r % NN;
    const float* ncb = g_nc + b*3*NN;
    int vx = (int)rintf(ncb[n]);
    int vy = (int)rintf(ncb[NN+n]);
    int vz = (int)rintf(ncb[2*NN+n]);
    int v = (vx*RR+vy)*RR+vz;
    if (c==0) atomicAdd(&g_cnt[b*VV+v], 1.f);
    atomicAdd(&g_grid[(b*VV+v)*64 + c], feat[(b*64+c)*NN + n]);
}

// 3x3x3 conv + bias + relu (unchanged)
__global__ void __launch_bounds__(256) k_conv(const float* __restrict__ bias) {
    extern __shared__ float sm[];
    float* sLine = sm;
    float* sW    = sm + 13056;
    float* sCnt  = sm + 19200;
    int blk = blockIdx.x;
    int yg = blk & 7;
    int x  = (blk>>3) & 31;
    int b  = blk >> 8;
    int y0 = yg*4;
    int t  = threadIdx.x;
    int coq = t & 15;
    int yi  = (t >> 4) & 3;
    int zq  = t >> 6;
    ull acc[2][8];
    #pragma unroll
    for (int p=0; p<2; p++)
        #pragma unroll
        for (int z=0; z<8; z++) acc[p][z]=0ULL;

    for (int dx=0; dx<3; dx++) {
        __syncthreads();
        int xx = x + dx - 1;
        bool vx = (xx>=0 && xx<32);
        if (t < 204) {
            int yy = t/34, zz = t%34;
            int y = y0 - 1 + yy, z = zz - 1;
            float c = 1.f;
            if (vx && y>=0 && y<32 && z>=0 && z<32)
                c = fmaxf(g_cnt[b*VV + (xx*32+y)*32 + z], 1.f);
            sCnt[t] = __fdividef(1.f, c);
        }
        __syncthreads();
        for (int i=t; i<13056; i+=256) {
            int ci = i & 63;
            int zz = (i>>6) % 34;
            int yy = i / 2176;
            int y = y0 - 1 + yy, z = zz - 1;
            float val = 0.f;
            if (vx && y>=0 && y<32 && z>=0 && z<32)
                val = g_grid[(b*VV + (xx*32+y)*32 + z)*64 + ci] * sCnt[yy*34+zz];
            sLine[i] = val;
        }
        for (int dy=0; dy<3; dy++) {
            const float* wsrc = g_wt + (dx*3+dy)*12288;
            for (int ch=0; ch<2; ch++) {
                __syncthreads();
                for (int i=t; i<6144; i+=256) {
                    int kz = i / 2048;
                    int rem = i % 2048;
                    sW[i] = wsrc[kz*4096 + ch*2048 + rem];
                }
                __syncthreads();
                const float* Lb = sLine + (yi+dy)*2176 + zq*512 + ch*32;
                for (int cil=0; cil<32; cil++) {
                    const float* wb = sW + cil*64 + coq*4;
                    ull w0a = *(const ull*)(wb);
                    ull w0b = *(const ull*)(wb+2);
                    ull w1a = *(const ull*)(wb+2048);
                    ull w1b = *(const ull*)(wb+2050);
                    ull w2a = *(const ull*)(wb+4096);
                    ull w2b = *(const ull*)(wb+4098);
                    const float* L = Lb + cil;
                    float l0 = L[0], l1 = L[64];
                    ull p0 = pack2(l0,l0), p1 = pack2(l1,l1);
                    #pragma unroll
                    for (int z=0; z<8; z++) {
                        float l2 = L[(z+2)*64];
                        ull p2 = pack2(l2,l2);
                        fma2(acc[0][z], w0a, p0); fma2(acc[1][z], w0b, p0);
                        fma2(acc[0][z], w1a, p1); fma2(acc[1][z], w1b, p1);
                        fma2(acc[0][z], w2a, p2); fma2(acc[1][z], w2b, p2);
                        p0=p1; p1=p2;
                    }
                }
            }
        }
    }
    float b0 = bias[coq*4], b1 = bias[coq*4+1], b2 = bias[coq*4+2], b3 = bias[coq*4+3];
    int ybase = b*VV + (x*32 + y0 + yi)*32 + zq*8;
    #pragma unroll
    for (int z=0; z<8; z++) {
        float2 fa = unpack2(acc[0][z]);
        float2 fb = unpack2(acc[1][z]);
        float4 o;
        o.x = fmaxf(fa.x + b0, 0.f);
        o.y = fmaxf(fa.y + b1, 0.f);
        o.z = fmaxf(fb.x + b2, 0.f);
        o.w = fmaxf(fb.y + b3, 0.f);
        *(float4*)&g_x[(ybase+z)*64 + coq*4] = o;
    }
}

// window attention with ci-pair GEMMs
__global__ void k_winattn(const float* __restrict__ g1, const float* __restrict__ bb1,
                          const float* __restrict__ qkvw, const float* __restrict__ qkvb,
                          const float* __restrict__ pw, const float* __restrict__ pb) {
    extern __shared__ float sm[];
    float* Hs = sm;
    float* Qs = sm + 4224;
    float* Ks = sm + 8448;
    float* Vs = sm + 12672;
    float* Wn = sm + 16896;    // 4096, swizzled
    __shared__ int vmap[64];
    int blk = blockIdx.x;
    int b = blk >> 9;
    int rr = blk & 511;
    int wx = rr>>6, wy = (rr>>3)&7, wz = rr&7;
    int t = threadIdx.x;
    if (t < 64) {
        int ix = t>>4, iy = (t>>2)&3, iz = t&3;
        int v = ((wx*4+ix)*32 + (wy*4+iy))*32 + (wz*4+iz);
        vmap[t] = v;
        const float* row = g_x + (b*VV + v)*64;
        float mean=0.f, m2=0.f;
        for (int c=0;c<64;c++){ float xv=row[c]; mean+=xv; m2+=xv*xv; }
        mean *= 0.015625f;
        m2 = m2*0.015625f - mean*mean;
        float rs = rsqrtf(m2 + 1e-5f);
        for (int c=0;c<64;c++) Hs[t*WS+c] = (row[c]-mean)*rs*g1[c] + bb1[c];
    }
    int r = t>>4, q = t&15;
    for (int cc=0; cc<3; cc++) {
        __syncthreads();
        STAGE_W(Wn, qkvw[(cc*64+jj_)*64+ci_])
        __syncthreads();
        ull acc[4][4];
        #pragma unroll
        for (int i=0;i<4;i++)
            #pragma unroll
            for (int j=0;j<4;j++) acc[i][j]=0ULL;
        GEMM_P(acc, Hs, Wn)
        float* dst = (cc==0)?Qs:((cc==1)?Ks:Vs);
        #pragma unroll
        for (int i=0;i<4;i++)
            #pragma unroll
            for (int j=0;j<4;j++) {
                float2 f = unpack2(acc[i][j]);
                dst[(r*4+i)*WS + q*4+j] = f.x + f.y + qkvb[cc*64+q*4+j];
            }
    }
    __syncthreads();
    {   // attention: thread = (tok, head)
        int tok = t&63, h = t>>6;
        ull q2[8], o2[8];
        const ull* qrow = (const ull*)&Qs[tok*WS + h*16];
        #pragma unroll
        for (int k=0;k<8;k++){ q2[k]=qrow[k]; o2[k]=0ULL; }
        float mx = -3e30f, ss = 0.f;
        for (int m=0; m<64; m++) {
            const ull* kr = (const ull*)&Ks[m*WS + h*16];
            ull sp = 0ULL;
            #pragma unroll
            for (int k=0;k<8;k++) fma2(sp, q2[k], kr[k]);
            float2 sf = unpack2(sp);
            float s = (sf.x + sf.y)*0.25f;
            if (s > mx) {
                float cr = __expf(mx - s);
                ss *= cr;
                ull cp = pack2(cr,cr);
                #pragma unroll
                for (int k=0;k<8;k++) mul2(o2[k], cp);
                mx = s;
            }
            float wv = __expf(s - mx);
            ss += wv;
            ull wp = pack2(wv,wv);
            const ull* vr = (const ull*)&Vs[m*WS + h*16];
            #pragma unroll
            for (int k=0;k<8;k++) fma2(o2[k], vr[k], wp);
        }
        float inv = 1.f/ss;
        #pragma unroll
        for (int k=0;k<8;k++) {
            float2 f = unpack2(o2[k]);
            Hs[tok*WS + h*16 + 2*k]   = f.x*inv;
            Hs[tok*WS + h*16 + 2*k+1] = f.y*inv;
        }
    }
    __syncthreads();
    STAGE_W(Wn, pw[jj_*64+ci_])
    __syncthreads();
    {
        ull acc[4][4];
        #pragma unroll
        for (int i=0;i<4;i++)
            #pragma unroll
            for (int j=0;j<4;j++) acc[i][j]=0ULL;
        GEMM_P(acc, Hs, Wn)
        #pragma unroll
        for (int i=0;i<4;i++)
            #pragma unroll
            for (int j=0;j<4;j++) {
                float2 f = unpack2(acc[i][j]);
                g_x[(b*VV + vmap[r*4+i])*64 + q*4+j] += f.x + f.y + pb[q*4+j];
            }
    }
}

// LN2 + MLP(gelu-tanh via exp) + residual
__global__ void k_mlp(const float* __restrict__ g2, const float* __restrict__ b2g,
                      const float* __restrict__ w1, const float* __restrict__ mb1,
                      const float* __restrict__ w2, const float* __restrict__ mb2) {
    extern __shared__ float sm[];
    float* Aa = sm;            // stride 66
    float* Hc = sm + 4224;
    float* Wn = sm + 8448;     // 4096 swizzled
    int t = threadIdx.x;
    int gt0 = blockIdx.x*64;
    if (t < 64) {
        const float* row = g_x + (gt0+t)*64;
        float mean=0.f, m2=0.f;
        for (int c=0;c<64;c++){ float xv=row[c]; mean+=xv; m2+=xv*xv; }
        mean *= 0.015625f;
        m2 = m2*0.015625f - mean*mean;
        float rs = rsqrtf(m2 + 1e-5f);
        for (int c=0;c<64;c++) Aa[t*WS+c] = (row[c]-mean)*rs*g2[c] + b2g[c];
    }
    int r = t>>4, q = t&15;
    ull o2[4][4];
    #pragma unroll
    for (int i=0;i<4;i++)
        #pragma unroll
        for (int j=0;j<4;j++) o2[i][j]=0ULL;
    for (int ch=0; ch<4; ch++) {
        __syncthreads();
        STAGE_W(Wn, w1[(ch*64+jj_)*64+ci_])
        __syncthreads();
        ull h2[4][4];
        #pragma unroll
        for (int i=0;i<4;i++)
            #pragma unroll
            for (int j=0;j<4;j++) h2[i][j]=0ULL;
        GEMM_P(h2, Aa, Wn)
        __syncthreads();
        #pragma unroll
        for (int i=0;i<4;i++)
            #pragma unroll
            for (int j=0;j<4;j++) {
                float2 f = unpack2(h2[i][j]);
                float xv = f.x + f.y + mb1[ch*64+q*4+j];
                float u = 1.5957691216f*(xv + 0.044715f*xv*xv*xv);
                float tt = 1.f - __fdividef(2.f, 1.f + __expf(u));
                Hc[(r*4+i)*WS + q*4+j] = 0.5f*xv*(1.f + tt);
            }
        __syncthreads();
        STAGE_W(Wn, w2[jj_*256 + ch*64 + ci_])
        __syncthreads();
        GEMM_P(o2, Hc, Wn)
    }
    #pragma unroll
    for (int i=0;i<4;i++)
        #pragma unroll
        for (int j=0;j<4;j++) {
            float2 f = unpack2(o2[i][j]);
            g_x[(gt0 + r*4+i)*64 + q*4+j] += f.x + f.y + mb2[q*4+j];
        }
}

__global__ void k_sereduce() {
    int blk = blockIdx.x;
    int b = blk>>5, chunk = blk&31;
    int t = threadIdx.x;
    const float* base = g_x + (b*VV + chunk*1024)*64;
    float s = 0.f;
    for (int i=t; i<65536; i+=256) s += base[i];
    __shared__ float red[256];
    red[t]=s; __syncthreads();
    if (t < 64) {
        float v = red[t]+red[t+64]+red[t+128]+red[t+192];
        atomicAdd(&g_semean[b*64 + t], v);
    }
}

__global__ void k_se(const float* __restrict__ w1, const float* __restrict__ w2) {
    int t = threadIdx.x;
    int b = t>>6, c = t&63;
    __shared__ float hid[4][8];
    if (c < 8) {
        float a = 0.f;
        for (int ci=0;ci<64;ci++) a += w1[c*64+ci]*g_semean[b*64+ci];
        a *= (1.f/VV);
        hid[b][c] = fmaxf(a, 0.f);
    }
    __syncthreads();
    float s = 0.f;
    for (int j=0;j<8;j++) s += w2[c*8+j]*hid[b][j];
    g_se[b*64+c] = 1.f/(1.f + __expf(-s));
}

__global__ void k_pointmaps(const float* __restrict__ feat, const float* __restrict__ pw,
                            const float* __restrict__ pb, const float* __restrict__ qw,
                            const float* __restrict__ kw, const float* __restrict__ vw) {
    __shared__ float F[4224];     // stride 66
    __shared__ float Wn[4096];    // swizzled (or plain for qk)
    int blk = blockIdx.x;
    int b = blk>>6;
    int n0 = (blk&63)*64;
    int t = threadIdx.x;
    for (int i=t; i<4096; i+=256){ int pt=i&63, ci=i>>6; F[pt*WS+ci] = feat[(b*64+ci)*NN + n0+pt]; }
    STAGE_W(Wn, pw[jj_*64+ci_])
    __syncthreads();
    int r = t>>4, q = t&15;
    {
        ull acc[4][4];
        #pragma unroll
        for (int i=0;i<4;i++)
            #pragma unroll
            for (int j=0;j<4;j++) acc[i][j]=0ULL;
        GEMM_P(acc, F, Wn)
        __syncthreads();
        #pragma unroll
        for (int i=0;i<4;i++)
            #pragma unroll
            for (int j=0;j<4;j++) {
                float2 f = unpack2(acc[i][j]);
                float v = fmaxf(f.x + f.y + pb[q*4+j], 0.f);
                F[(r*4+i)*WS + q*4+j] = v;
                g_px[(b*NN + n0 + r*4+i)*64 + q*4+j] = v;
            }
    }
    __syncthreads();
    for (int i=t; i<1024; i+=256) Wn[i] = qw[i];
    for (int i=t; i<1024; i+=256) Wn[1024+i] = kw[i];
    __syncthreads();
    {
        int pt = t&63, dh = t>>6;
        for (int dl=0; dl<4; dl++) {
            int d = dh*4 + dl;
            ull aq2=0ULL, ak2=0ULL;
            for (int cp=0; cp<32; cp++) {
                ull xv = *(const ull*)&F[pt*WS + 2*cp];
                fma2(aq2, xv, *(const ull*)&Wn[d*64 + 2*cp]);
                fma2(ak2, xv, *(const ull*)&Wn[1024 + d*64 + 2*cp]);
            }
            float2 fq = unpack2(aq2), fk = unpack2(ak2);
            g_pq[(b*NN+n0+pt)*16 + d] = fq.x + fq.y;
            g_pk[(b*NN+n0+pt)*16 + d] = fk.x + fk.y;
        }
    }
    __syncthreads();
    STAGE_W(Wn, vw[jj_*64+ci_])
    __syncthreads();
    {
        ull acc[4][4];
        #pragma unroll
        for (int i=0;i<4;i++)
            #pragma unroll
            for (int j=0;j<4;j++) acc[i][j]=0ULL;
        GEMM_P(acc, F, Wn)
        #pragma unroll
        for (int i=0;i<4;i++)
            #pragma unroll
            for (int j=0;j<4;j++) {
                float2 f = unpack2(acc[i][j]);
                g_pv[(b*NN + n0 + r*4+i)*64 + q*4+j] = f.x + f.y;
            }
    }
}

// flash-style point attention, key-split into 4 segments of 1024
__global__ void k_pointattn() {
    __shared__ __align__(16) float Ks[2048];
    __shared__ __align__(16) float Vs[8192];
    int blk = blockIdx.x;
    int b = blk >> 6;
    int rem = blk & 63;
    int qg = rem >> 2;
    int seg = rem & 3;
    int t = threadIdx.x;
    int n = qg*256 + t;
    int bn = b*NN + n;
    ull q2[8];
    {
        const ull* qp = (const ull*)&g_pq[bn*16];
        #pragma unroll
        for (int k=0;k<8;k++) q2[k] = qp[k];
    }
    ull o2[32];
    #pragma unroll
    for (int k=0;k<32;k++) o2[k]=0ULL;
    float mx=-3e30f, ss=0.f;
    int m0base = seg*1024;
    for (int tile=0; tile<8; tile++) {
        int m0 = m0base + tile*128;
        __syncthreads();
        const float4* ksrc = (const float4*)&g_pk[(b*NN+m0)*16];
        float4* kdst = (float4*)Ks;
        for (int i=t; i<512; i+=256) kdst[i] = ksrc[i];
        const float4* vsrc = (const float4*)&g_pv[(b*NN+m0)*64];
        float4* vdst = (float4*)Vs;
        for (int i=t; i<2048; i+=256) vdst[i] = vsrc[i];
        __syncthreads();
        for (int mm=0; mm<128; mm++) {
            const ull* kr = (const ull*)&Ks[mm*16];
            ull sp = 0ULL;
            #pragma unroll
            for (int k=0;k<8;k++) fma2(sp, q2[k], kr[k]);
            float2 sf = unpack2(sp);
            float s = (sf.x + sf.y)*0.25f;
            if (s > mx) {
                float cr = __expf(mx - s);
                ss *= cr;
                ull cp = pack2(cr, cr);
                #pragma unroll
                for (int k=0;k<32;k++) mul2(o2[k], cp);
                mx = s;
            }
            float w = __expf(s - mx);
            ss += w;
            ull wp = pack2(w, w);
            const ulonglong2* vr = (const ulonglong2*)&Vs[mm*64];
            #pragma unroll
            for (int k=0;k<16;k++) {
                ulonglong2 vv = vr[k];
                fma2(o2[2*k],   vv.x, wp);
                fma2(o2[2*k+1], vv.y, wp);
            }
        }
    }
    g_pmx[seg*(BB*NN) + bn] = mx;
    g_pss[seg*(BB*NN) + bn] = ss;
    float inv = 1.f/ss;
    float2* dst = (float2*)&g_pop[(size_t)seg*BB*NN*64 + (size_t)bn*64];
    #pragma unroll
    for (int k=0;k<32;k++) {
        float2 f = unpack2(o2[k]);
        f.x *= inv; f.y *= inv;
        dst[k] = f;
    }
}

// merge 4 attn segments; off = relu(tw@(px-po)+tb); g_po := px + off
__global__ void k_trans(const float* __restrict__ tw, const float* __restrict__ tb) {
    __shared__ float D[4224];     // stride 66
    __shared__ float Wn[4096];
    __shared__ float Aw[320];
    int blk = blockIdx.x;
    int b = blk>>6;
    int n0 = (blk&63)*64;
    int t = threadIdx.x;
    if (t < 64) {
        int bn = b*NN + n0 + t;
        float m[4], s[4];
        float mm = -3e30f;
        #pragma unroll
        for (int sg=0; sg<4; sg++) {
            m[sg] = g_pmx[sg*(BB*NN)+bn];
            s[sg] = g_pss[sg*(BB*NN)+bn];
            mm = fmaxf(mm, m[sg]);
        }
        float den = 0.f;
        #pragma unroll
        for (int sg=0; sg<4; sg++) {
            float a = s[sg]*__expf(m[sg]-mm);
            Aw[t*5+sg] = a;
            den += a;
        }
        Aw[t*5+4] = 1.f/den;
    }
    __syncthreads();
    for (int i=t; i<4096; i+=256){
        int pt=i>>6, c=i&63;
        int bn = b*NN + n0 + pt;
        float po = 0.f;
        #pragma unroll
        for (int sg=0; sg<4; sg++)
            po += g_pop[(size_t)sg*BB*NN*64 + (size_t)bn*64 + c]*Aw[pt*5+sg];
        po *= Aw[pt*5+4];
        D[pt*WS+c] = g_px[bn*64+c] - po;
    }
    STAGE_W(Wn, tw[jj_*64+ci_])
    __syncthreads();
    int r = t>>4, q = t&15;
    ull acc[4][4];
    #pragma unroll
    for (int i=0;i<4;i++)
        #pragma unroll
        for (int j=0;j<4;j++) acc[i][j]=0ULL;
    GEMM_P(acc, D, Wn)
    #pragma unroll
    for (int i=0;i<4;i++)
        #pragma unroll
        for (int j=0;j<4;j++) {
            float2 f = unpack2(acc[i][j]);
            int gi = (b*NN+n0+r*4+i)*64 + q*4+j;
            g_po[gi] = g_px[gi] + fmaxf(f.x + f.y + tb[q*4+j], 0.f);
        }
}

// devoxelize(trilinear) * SE + point branch -> d_out
__global__ void k_out(float* __restrict__ out) {
    __shared__ int idxS[512];
    __shared__ float wS[512];
    __shared__ float obuf[4160];
    int blk = blockIdx.x;
    int b = blk>>6;
    int n0 = (blk&63)*64;
    int t = threadIdx.x;
    if (t < 64) {
        int n = n0 + t;
        const float* ncb = g_nc + b*3*NN;
        float f0=ncb[n], f1=ncb[NN+n], f2=ncb[2*NN+n];
        float fl0=floorf(f0), fl1=floorf(f1), fl2=floorf(f2);
        int x0=(int)fl0, y0=(int)fl1, z0=(int)fl2;
        float a0=f0-fl0, a1=f1-fl1, a2=f2-fl2;
        for (int k=0;k<8;k++){
            int dx=k>>2, dy=(k>>1)&1, dz=k&1;
            int xi=min(x0+dx,31), yi=min(y0+dy,31), zi=min(z0+dz,31);
            idxS[t*8+k] = (xi*32+yi)*32+zi;
            wS[t*8+k] = (dx?a0:1.f-a0)*(dy?a1:1.f-a1)*(dz?a2:1.f-a2);
        }
    }
    __syncthreads();
    int c = t&63, sub = t>>6;
    float sec = g_se[b*64+c];
    for (int nq=0; nq<16; nq++) {
        int nl = nq*4 + sub;
        float v = 0.f;
        #pragma unroll
        for (int k=0;k<8;k++)
            v += g_x[(b*VV + idxS[nl*8+k])*64 + c]*wS[nl*8+k];
        obuf[nl*65 + c] = v*sec + g_po[(b*NN+n0+nl)*64+c];
    }
    __syncthreads();
    for (int i=t; i<4096; i+=256) {
        int cc = i>>6, nl = i&63;
        out[(b*64+cc)*NN + n0+nl] = obuf[nl*65+cc];
    }
}

__global__ void k_copy(float* __restrict__ out, const float* __restrict__ coords) {
    int i = blockIdx.x*256 + threadIdx.x;
    if (i < BB*3*NN) out[BB*64*NN + i] = coords[i];
}

extern "C" void kernel_launch(void* const* d_in, const int* in_sizes, int n_in,
                              void* d_out, int out_size) {
    const float* feat   = (const float*)d_in[0];
    const float* coords = (const float*)d_in[1];
    const float* convw  = (const float*)d_in[2];
    const float* convb  = (const float*)d_in[3];
    const float* ln1g   = (const float*)d_in[4];
    const float* ln1b   = (const float*)d_in[5];
    const float* qkvw   = (const float*)d_in[6];
    const float* qkvb   = (const float*)d_in[7];
    const float* projw  = (const float*)d_in[8];
    const float* projb  = (const float*)d_in[9];
    const float* ln2g   = (const float*)d_in[10];
    const float* ln2b   = (const float*)d_in[11];
    const float* mw1    = (const float*)d_in[12];
    const float* mb1    = (const float*)d_in[13];
    const float* mw2    = (const float*)d_in[14];
    const float* mb2    = (const float*)d_in[15];
    const float* sew1   = (const float*)d_in[16];
    const float* sew2   = (const float*)d_in[17];
    const float* ptw    = (const float*)d_in[18];
    const float* ptb    = (const float*)d_in[19];
    const float* qw     = (const float*)d_in[20];
    const float* kw     = (const float*)d_in[21];
    const float* vw     = (const float*)d_in[22];
    const float* tw     = (const float*)d_in[23];
    const float* tb     = (const float*)d_in[24];
    float* out = (float*)d_out;

    cudaFuncSetAttribute(k_conv,    cudaFuncAttributeMaxDynamicSharedMemorySize, 77616);
    cudaFuncSetAttribute(k_winattn, cudaFuncAttributeMaxDynamicSharedMemorySize, 83968);
    cudaFuncSetAttribute(k_mlp,     cudaFuncAttributeMaxDynamicSharedMemorySize, 50176);

    k_initstats<<<8196, 256>>>(convw, coords);
    k_scatter<<<4096, 256>>>(feat);
    k_conv<<<1024, 256, 77616>>>(convb);
    k_winattn<<<2048, 256, 83968>>>(ln1g, ln1b, qkvw, qkvb, projw, projb); // launch #4 -> profiled
    k_mlp<<<2048, 256, 50176>>>(ln2g, ln2b, mw1, mb1, mw2, mb2);
    k_sereduce<<<128, 256>>>();
    k_se<<<1, 256>>>(sew1, sew2);
    k_pointmaps<<<256, 256>>>(feat, ptw, ptb, qw, kw, vw);
    k_pointattn<<<256, 256>>>();
    k_trans<<<256, 256>>>(tw, tb);
    k_out<<<256, 256>>>(out);
    if (out_size >= BB*64*NN + BB*3*NN)
        k_copy<<<192, 256>>>(out, coords);
}

// round 10
// speedup vs baseline: 1.0474x; 1.0474x over previous
#include <cuda_runtime.h>
#include <math.h>

#define BB 4
#define NN 4096
#define RR 32
#define VV (RR*RR*RR)

__device__ float g_grid[BB*VV*64];
__device__ float g_cnt[BB*VV];
__device__ float g_nc[BB*3*NN];
__device__ float g_x[BB*VV*64];
__device__ float g_wt[9*3*64*64];
__device__ float g_semean[BB*64];
__device__ float g_se[BB*64];
__device__ float g_px[BB*NN*64];
__device__ float g_pq[BB*NN*16];
__device__ float g_pk[BB*NN*16];
__device__ float g_pv[BB*NN*64];
__device__ float g_pop[4*BB*NN*64];
__device__ float g_po[BB*NN*64];
__device__ float g_pmx[4*BB*NN];
__device__ float g_pss[4*BB*NN];

typedef unsigned long long ull;

__device__ __forceinline__ ull pack2(float x, float y) {
    ull r; asm("mov.b64 %0, {%1, %2};" : "=l"(r) : "f"(x), "f"(y)); return r;
}
__device__ __forceinline__ float2 unpack2(ull v) {
    float2 f; asm("mov.b64 {%0, %1}, %2;" : "=f"(f.x), "=f"(f.y) : "l"(v)); return f;
}
__device__ __forceinline__ void fma2(ull &d, ull a, ull b) {
    asm("fma.rn.f32x2 %0, %1, %2, %0;" : "+l"(d) : "l"(a), "l"(b));
}
__device__ __forceinline__ void mul2(ull &d, ull a) {
    asm("mul.rn.f32x2 %0, %0, %1;" : "+l"(d) : "l"(a));
}

#define WS 66

// Stage 64x64 weight W[jj][ci] into interleaved-pair layout:
//   Wn[ci*128 + ((jj>>1)&1)*64 + 2*((jj>>2) ^ (ci&15)) + (jj&1)]
// Reader (lane q) loads pair (w[q*4],w[q*4+1]) at group q^(ci&15): conflict-free.
#define STAGE_W(WN, SRCROW) \
    for (int i_=threadIdx.x; i_<4096; i_+=256){ \
        int jj_=i_>>6, ci_=i_&63; \
        (WN)[ci_*128 + ((jj_>>1)&1)*64 + 2*((jj_>>2) ^ (ci_&15)) + (jj_&1)] = (SRCROW); \
    }

// GEMM microkernel: ACC[i][jp] += A[(r*4+i)][ci] * W[q*4+2jp..+1][ci]
#define GEMM_TW(ACC, ABUF, WT) \
    for (int ci=0; ci<64; ci++) { \
        int wb_ = ci*128 + 2*(q ^ (ci&15)); \
        ull w01 = *(const ull*)&(WT)[wb_]; \
        ull w23 = *(const ull*)&(WT)[wb_ + 64]; \
        _Pragma("unroll") \
        for (int i=0;i<4;i++) { \
            float av = (ABUF)[(r*4+i)*WS+ci]; \
            ull ap = pack2(av,av); \
            fma2(ACC[i][0], ap, w01); \
            fma2(ACC[i][1], ap, w23); \
        } \
    }

// fused init (zero + conv weight transpose) + per-batch coord stats
__global__ void k_initstats(const float* __restrict__ w, const float* __restrict__ coords) {
    int blk = blockIdx.x;
    int t = threadIdx.x;
    if (blk < 8192) {
        int i = blk*256 + t;
        if (i < BB*VV*64/4) ((float4*)g_grid)[i] = make_float4(0.f,0.f,0.f,0.f);
        if (i < BB*VV)      g_cnt[i] = 0.f;
        if (i < BB*64)      g_semean[i] = 0.f;
        if (i < 9*3*64*64) {
            int co = i & 63;
            int ci = (i>>6) & 63;
            int kz = (i>>12) % 3;
            int g  = i / 12288;
            int dx = g/3, dy = g%3;
            g_wt[i] = w[(((co*64+ci)*3+dx)*3+dy)*3 + kz];
        }
        return;
    }
    int b = blk - 8192;
    __shared__ float red[256];
    __shared__ float mS[3], mxS;
    const float* cb = coords + b*3*NN;
    float s0=0.f, s1=0.f, s2=0.f;
    for (int n=t; n<NN; n+=256) { s0+=cb[n]; s1+=cb[NN+n]; s2+=cb[2*NN+n]; }
    float sv[3] = {s0,s1,s2};
    for (int d=0; d<3; d++) {
        red[t]=sv[d]; __syncthreads();
        for (int o=128;o;o>>=1){ if(t<o) red[t]+=red[t+o]; __syncthreads(); }
        if (t==0) mS[d] = red[0]*(1.f/NN);
        __syncthreads();
    }
    float m0=mS[0], m1=mS[1], m2=mS[2];
    float mx = 0.f;
    for (int n=t; n<NN; n+=256) {
        float dx=cb[n]-m0, dy=cb[NN+n]-m1, dz=cb[2*NN+n]-m2;
        mx = fmaxf(mx, dx*dx+dy*dy+dz*dz);
    }
    red[t]=mx; __syncthreads();
    for (int o=128;o;o>>=1){ if(t<o) red[t]=fmaxf(red[t],red[t+o]); __syncthreads(); }
    if (t==0) mxS = sqrtf(red[0]);
    __syncthreads();
    float inv = 1.f/(2.f*mxS);
    float* ncb = g_nc + b*3*NN;
    for (int n=t; n<NN; n+=256) {
        float v0 = ((cb[n]      -m0)*inv + 0.5f)*RR;
        float v1 = ((cb[NN+n]   -m1)*inv + 0.5f)*RR;
        float v2 = ((cb[2*NN+n] -m2)*inv + 0.5f)*RR;
        ncb[n]      = fminf(fmaxf(v0,0.f), 31.f);
        ncb[NN+n]   = fminf(fmaxf(v1,0.f), 31.f);
        ncb[2*NN+n] = fminf(fmaxf(v2,0.f), 31.f);
    }
}

__global__ void k_scatter(const float* __restrict__ feat) {
    int i = blockIdx.x*256 + threadIdx.x;
    const int PN = BB*NN;
    if (i >= 64*PN) return;
    int c = i / PN;
    int r = i % PN;
    int b = r / NN, n = r % NN;
    const float* ncb = g_nc + b*3*NN;
    int vx = (int)rintf(ncb[n]);
    int vy = (int)rintf(ncb[NN+n]);
    int vz = (int)rintf(ncb[2*NN+n]);
    int v = (vx*RR+vy)*RR+vz;
    if (c==0) atomicAdd(&g_cnt[b*VV+v], 1.f);
    atomicAdd(&g_grid[(b*VV+v)*64 + c], feat[(b*64+c)*NN + n]);
}

// 3x3x3 conv + bias + relu (unchanged, round-7 best)
__global__ void __launch_bounds__(256) k_conv(const float* __restrict__ bias) {
    extern __shared__ float sm[];
    float* sLine = sm;
    float* sW    = sm + 13056;
    float* sCnt  = sm + 19200;
    int blk = blockIdx.x;
    int yg = blk & 7;
    int x  = (blk>>3) & 31;
    int b  = blk >> 8;
    int y0 = yg*4;
    int t  = threadIdx.x;
    int coq = t & 15;
    int yi  = (t >> 4) & 3;
    int zq  = t >> 6;
    ull acc[2][8];
    #pragma unroll
    for (int p=0; p<2; p++)
        #pragma unroll
        for (int z=0; z<8; z++) acc[p][z]=0ULL;

    for (int dx=0; dx<3; dx++) {
        __syncthreads();
        int xx = x + dx - 1;
        bool vx = (xx>=0 && xx<32);
        if (t < 204) {
            int yy = t/34, zz = t%34;
            int y = y0 - 1 + yy, z = zz - 1;
            float c = 1.f;
            if (vx && y>=0 && y<32 && z>=0 && z<32)
                c = fmaxf(g_cnt[b*VV + (xx*32+y)*32 + z], 1.f);
            sCnt[t] = __fdividef(1.f, c);
        }
        __syncthreads();
        for (int i=t; i<13056; i+=256) {
            int ci = i & 63;
            int zz = (i>>6) % 34;
            int yy = i / 2176;
            int y = y0 - 1 + yy, z = zz - 1;
            float val = 0.f;
            if (vx && y>=0 && y<32 && z>=0 && z<32)
                val = g_grid[(b*VV + (xx*32+y)*32 + z)*64 + ci] * sCnt[yy*34+zz];
            sLine[i] = val;
        }
        for (int dy=0; dy<3; dy++) {
            const float* wsrc = g_wt + (dx*3+dy)*12288;
            for (int ch=0; ch<2; ch++) {
                __syncthreads();
                for (int i=t; i<6144; i+=256) {
                    int kz = i / 2048;
                    int rem = i % 2048;
                    sW[i] = wsrc[kz*4096 + ch*2048 + rem];
                }
                __syncthreads();
                const float* Lb = sLine + (yi+dy)*2176 + zq*512 + ch*32;
                for (int cil=0; cil<32; cil++) {
                    const float* wb = sW + cil*64 + coq*4;
                    ull w0a = *(const ull*)(wb);
                    ull w0b = *(const ull*)(wb+2);
                    ull w1a = *(const ull*)(wb+2048);
                    ull w1b = *(const ull*)(wb+2050);
                    ull w2a = *(const ull*)(wb+4096);
                    ull w2b = *(const ull*)(wb+4098);
                    const float* L = Lb + cil;
                    float l0 = L[0], l1 = L[64];
                    ull p0 = pack2(l0,l0), p1 = pack2(l1,l1);
                    #pragma unroll
                    for (int z=0; z<8; z++) {
                        float l2 = L[(z+2)*64];
                        ull p2 = pack2(l2,l2);
                        fma2(acc[0][z], w0a, p0); fma2(acc[1][z], w0b, p0);
                        fma2(acc[0][z], w1a, p1); fma2(acc[1][z], w1b, p1);
                        fma2(acc[0][z], w2a, p2); fma2(acc[1][z], w2b, p2);
                        p0=p1; p1=p2;
                    }
                }
            }
        }
    }
    float b0 = bias[coq*4], b1 = bias[coq*4+1], b2 = bias[coq*4+2], b3 = bias[coq*4+3];
    int ybase = b*VV + (x*32 + y0 + yi)*32 + zq*8;
    #pragma unroll
    for (int z=0; z<8; z++) {
        float2 fa = unpack2(acc[0][z]);
        float2 fb = unpack2(acc[1][z]);
        float4 o;
        o.x = fmaxf(fa.x + b0, 0.f);
        o.y = fmaxf(fa.y + b1, 0.f);
        o.z = fmaxf(fb.x + b2, 0.f);
        o.w = fmaxf(fb.y + b3, 0.f);
        *(float4*)&g_x[(ybase+z)*64 + coq*4] = o;
    }
}

// window attention; interleaved-pair weights (stride 128)
__global__ void k_winattn(const float* __restrict__ g1, const float* __restrict__ bb1,
                          const float* __restrict__ qkvw, const float* __restrict__ qkvb,
                          const float* __restrict__ pw, const float* __restrict__ pb) {
    extern __shared__ float sm[];
    float* Hs = sm;
    float* Qs = sm + 4224;
    float* Ks = sm + 8448;
    float* Vs = sm + 12672;
    float* Wn = sm + 16896;    // 8192 floats
    __shared__ int vmap[64];
    int blk = blockIdx.x;
    int b = blk >> 9;
    int rr = blk & 511;
    int wx = rr>>6, wy = (rr>>3)&7, wz = rr&7;
    int t = threadIdx.x;
    if (t < 64) {
        int ix = t>>4, iy = (t>>2)&3, iz = t&3;
        int v = ((wx*4+ix)*32 + (wy*4+iy))*32 + (wz*4+iz);
        vmap[t] = v;
        const float* row = g_x + (b*VV + v)*64;
        float mean=0.f, m2=0.f;
        for (int c=0;c<64;c++){ float xv=row[c]; mean+=xv; m2+=xv*xv; }
        mean *= 0.015625f;
        m2 = m2*0.015625f - mean*mean;
        float rs = rsqrtf(m2 + 1e-5f);
        for (int c=0;c<64;c++) Hs[t*WS+c] = (row[c]-mean)*rs*g1[c] + bb1[c];
    }
    int r = t>>4, q = t&15;
    for (int cc=0; cc<3; cc++) {
        __syncthreads();
        STAGE_W(Wn, qkvw[(cc*64+jj_)*64+ci_])
        __syncthreads();
        ull acc[4][2];
        {
            ull b0 = pack2(qkvb[cc*64+q*4],   qkvb[cc*64+q*4+1]);
            ull b1 = pack2(qkvb[cc*64+q*4+2], qkvb[cc*64+q*4+3]);
            #pragma unroll
            for (int i=0;i<4;i++){ acc[i][0]=b0; acc[i][1]=b1; }
        }
        GEMM_TW(acc, Hs, Wn)
        float* dst = (cc==0)?Qs:((cc==1)?Ks:Vs);
        #pragma unroll
        for (int i=0;i<4;i++)
            #pragma unroll
            for (int jp=0;jp<2;jp++) {
                float2 f = unpack2(acc[i][jp]);
                *(float2*)&dst[(r*4+i)*WS + q*4 + 2*jp] = f;
            }
    }
    __syncthreads();
    {   // attention: thread = (tok, head)
        int tok = t&63, h = t>>6;
        ull q2[8], o2[8];
        const ull* qrow = (const ull*)&Qs[tok*WS + h*16];
        #pragma unroll
        for (int k=0;k<8;k++){ q2[k]=qrow[k]; o2[k]=0ULL; }
        float mx = -3e30f, ss = 0.f;
        for (int m=0; m<64; m++) {
            const ull* kr = (const ull*)&Ks[m*WS + h*16];
            ull sp = 0ULL;
            #pragma unroll
            for (int k=0;k<8;k++) fma2(sp, q2[k], kr[k]);
            float2 sf = unpack2(sp);
            float s = (sf.x + sf.y)*0.25f;
            if (s > mx) {
                float cr = __expf(mx - s);
                ss *= cr;
                ull cp = pack2(cr,cr);
                #pragma unroll
                for (int k=0;k<8;k++) mul2(o2[k], cp);
                mx = s;
            }
            float wv = __expf(s - mx);
            ss += wv;
            ull wp = pack2(wv,wv);
            const ull* vr = (const ull*)&Vs[m*WS + h*16];
            #pragma unroll
            for (int k=0;k<8;k++) fma2(o2[k], vr[k], wp);
        }
        float inv = 1.f/ss;
        #pragma unroll
        for (int k=0;k<8;k++) {
            float2 f = unpack2(o2[k]);
            Hs[tok*WS + h*16 + 2*k]   = f.x*inv;
            Hs[tok*WS + h*16 + 2*k+1] = f.y*inv;
        }
    }
    __syncthreads();
    STAGE_W(Wn, pw[jj_*64+ci_])
    __syncthreads();
    {
        ull acc[4][2];
        ull b0 = pack2(pb[q*4],   pb[q*4+1]);
        ull b1 = pack2(pb[q*4+2], pb[q*4+3]);
        #pragma unroll
        for (int i=0;i<4;i++){ acc[i][0]=b0; acc[i][1]=b1; }
        GEMM_TW(acc, Hs, Wn)
        #pragma unroll
        for (int i=0;i<4;i++)
            #pragma unroll
            for (int jp=0;jp<2;jp++) {
                float2 f = unpack2(acc[i][jp]);
                int gi = (b*VV + vmap[r*4+i])*64 + q*4 + 2*jp;
                g_x[gi]   += f.x;
                g_x[gi+1] += f.y;
            }
    }
}

// LN2 + MLP(gelu-tanh via exp) + residual; 64 tokens / block
__global__ void k_mlp(const float* __restrict__ g2, const float* __restrict__ b2g,
                      const float* __restrict__ w1, const float* __restrict__ mb1,
                      const float* __restrict__ w2, const float* __restrict__ mb2) {
    extern __shared__ float sm[];
    float* Aa = sm;            // stride 66
    float* Hc = sm + 4224;     // stride 66
    float* Wn = sm + 8448;     // 8192
    int t = threadIdx.x;
    int gt0 = blockIdx.x*64;
    if (t < 64) {
        const float* row = g_x + (gt0+t)*64;
        float mean=0.f, m2=0.f;
        for (int c=0;c<64;c++){ float xv=row[c]; mean+=xv; m2+=xv*xv; }
        mean *= 0.015625f;
        m2 = m2*0.015625f - mean*mean;
        float rs = rsqrtf(m2 + 1e-5f);
        for (int c=0;c<64;c++) Aa[t*WS+c] = (row[c]-mean)*rs*g2[c] + b2g[c];
    }
    int r = t>>4, q = t&15;
    ull o2[4][2];
    {
        ull b0 = pack2(mb2[q*4],   mb2[q*4+1]);
        ull b1 = pack2(mb2[q*4+2], mb2[q*4+3]);
        #pragma unroll
        for (int i=0;i<4;i++){ o2[i][0]=b0; o2[i][1]=b1; }
    }
    for (int ch=0; ch<4; ch++) {
        __syncthreads();
        STAGE_W(Wn, w1[(ch*64+jj_)*64+ci_])
        __syncthreads();
        ull h2[4][2];
        {
            ull b0 = pack2(mb1[ch*64+q*4],   mb1[ch*64+q*4+1]);
            ull b1 = pack2(mb1[ch*64+q*4+2], mb1[ch*64+q*4+3]);
            #pragma unroll
            for (int i=0;i<4;i++){ h2[i][0]=b0; h2[i][1]=b1; }
        }
        GEMM_TW(h2, Aa, Wn)
        __syncthreads();
        #pragma unroll
        for (int i=0;i<4;i++)
            #pragma unroll
            for (int jp=0;jp<2;jp++) {
                float2 f = unpack2(h2[i][jp]);
                float u0 = 1.5957691216f*(f.x + 0.044715f*f.x*f.x*f.x);
                float u1 = 1.5957691216f*(f.y + 0.044715f*f.y*f.y*f.y);
                float t0 = 1.f - __fdividef(2.f, 1.f + __expf(u0));
                float t1 = 1.f - __fdividef(2.f, 1.f + __expf(u1));
                float2 g;
                g.x = 0.5f*f.x*(1.f + t0);
                g.y = 0.5f*f.y*(1.f + t1);
                *(float2*)&Hc[(r*4+i)*WS + q*4 + 2*jp] = g;
            }
        __syncthreads();
        STAGE_W(Wn, w2[jj_*256 + ch*64 + ci_])
        __syncthreads();
        GEMM_TW(o2, Hc, Wn)
    }
    #pragma unroll
    for (int i=0;i<4;i++)
        #pragma unroll
        for (int jp=0;jp<2;jp++) {
            float2 f = unpack2(o2[i][jp]);
            int gi = (gt0 + r*4+i)*64 + q*4 + 2*jp;
            g_x[gi]   += f.x;
            g_x[gi+1] += f.y;
        }
}

__global__ void k_sereduce() {
    int blk = blockIdx.x;
    int b = blk>>5, chunk = blk&31;
    int t = threadIdx.x;
    const float* base = g_x + (b*VV + chunk*1024)*64;
    float s = 0.f;
    for (int i=t; i<65536; i+=256) s += base[i];
    __shared__ float red[256];
    red[t]=s; __syncthreads();
    if (t < 64) {
        float v = red[t]+red[t+64]+red[t+128]+red[t+192];
        atomicAdd(&g_semean[b*64 + t], v);
    }
}

__global__ void k_se(const float* __restrict__ w1, const float* __restrict__ w2) {
    int t = threadIdx.x;
    int b = t>>6, c = t&63;
    __shared__ float hid[4][8];
    if (c < 8) {
        float a = 0.f;
        for (int ci=0;ci<64;ci++) a += w1[c*64+ci]*g_semean[b*64+ci];
        a *= (1.f/VV);
        hid[b][c] = fmaxf(a, 0.f);
    }
    __syncthreads();
    float s = 0.f;
    for (int j=0;j<8;j++) s += w2[c*8+j]*hid[b][j];
    g_se[b*64+c] = 1.f/(1.f + __expf(-s));
}

__global__ void k_pointmaps(const float* __restrict__ feat, const float* __restrict__ pw,
                            const float* __restrict__ pb, const float* __restrict__ qw,
                            const float* __restrict__ kw, const float* __restrict__ vw) {
    extern __shared__ float sm[];
    float* F  = sm;          // 4224 (stride 66)
    float* Wn = sm + 4224;   // 8192
    int blk = blockIdx.x;
    int b = blk>>6;
    int n0 = (blk&63)*64;
    int t = threadIdx.x;
    for (int i=t; i<4096; i+=256){ int pt=i&63, ci=i>>6; F[pt*WS+ci] = feat[(b*64+ci)*NN + n0+pt]; }
    STAGE_W(Wn, pw[jj_*64+ci_])
    __syncthreads();
    int r = t>>4, q = t&15;
    {
        ull acc[4][2];
        ull b0 = pack2(pb[q*4],   pb[q*4+1]);
        ull b1 = pack2(pb[q*4+2], pb[q*4+3]);
        #pragma unroll
        for (int i=0;i<4;i++){ acc[i][0]=b0; acc[i][1]=b1; }
        GEMM_TW(acc, F, Wn)
        __syncthreads();
        #pragma unroll
        for (int i=0;i<4;i++)
            #pragma unroll
            for (int jp=0;jp<2;jp++) {
                float2 f = unpack2(acc[i][jp]);
                f.x = fmaxf(f.x, 0.f);
                f.y = fmaxf(f.y, 0.f);
                *(float2*)&F[(r*4+i)*WS + q*4 + 2*jp] = f;
                *(float2*)&g_px[(b*NN + n0 + r*4+i)*64 + q*4 + 2*jp] = f;
            }
    }
    __syncthreads();
    for (int i=t; i<1024; i+=256) Wn[i] = qw[i];
    for (int i=t; i<1024; i+=256) Wn[1024+i] = kw[i];
    __syncthreads();
    {
        int pt = t&63, dh = t>>6;
        for (int dl=0; dl<4; dl++) {
            int d = dh*4 + dl;
            float aq=0.f, ak=0.f;
            for (int ci=0; ci<64; ci++) {
                float xv = F[pt*WS+ci];
                aq += xv*Wn[d*64+ci];
                ak += xv*Wn[1024 + d*64+ci];
            }
            g_pq[(b*NN+n0+pt)*16 + d] = aq;
            g_pk[(b*NN+n0+pt)*16 + d] = ak;
        }
    }
    __syncthreads();
    STAGE_W(Wn, vw[jj_*64+ci_])
    __syncthreads();
    {
        ull acc[4][2];
        #pragma unroll
        for (int i=0;i<4;i++){ acc[i][0]=0ULL; acc[i][1]=0ULL; }
        GEMM_TW(acc, F, Wn)
        #pragma unroll
        for (int i=0;i<4;i++)
            #pragma unroll
            for (int jp=0;jp<2;jp++) {
                float2 f = unpack2(acc[i][jp]);
                *(float2*)&g_pv[(b*NN + n0 + r*4+i)*64 + q*4 + 2*jp] = f;
            }
    }
}

// flash-style point attention, key-split into 4 segments of 1024
__global__ void k_pointattn() {
    __shared__ __align__(16) float Ks[2048];
    __shared__ __align__(16) float Vs[8192];
    int blk = blockIdx.x;
    int b = blk >> 6;
    int rem = blk & 63;
    int qg = rem >> 2;
    int seg = rem & 3;
    int t = threadIdx.x;
    int n = qg*256 + t;
    int bn = b*NN + n;
    ull q2[8];
    {
        const ull* qp = (const ull*)&g_pq[bn*16];
        #pragma unroll
        for (int k=0;k<8;k++) q2[k] = qp[k];
    }
    ull o2[32];
    #pragma unroll
    for (int k=0;k<32;k++) o2[k]=0ULL;
    float mx=-3e30f, ss=0.f;
    int m0base = seg*1024;
    for (int tile=0; tile<8; tile++) {
        int m0 = m0base + tile*128;
        __syncthreads();
        const float4* ksrc = (const float4*)&g_pk[(b*NN+m0)*16];
        float4* kdst = (float4*)Ks;
        for (int i=t; i<512; i+=256) kdst[i] = ksrc[i];
        const float4* vsrc = (const float4*)&g_pv[(b*NN+m0)*64];
        float4* vdst = (float4*)Vs;
        for (int i=t; i<2048; i+=256) vdst[i] = vsrc[i];
        __syncthreads();
        for (int mm=0; mm<128; mm++) {
            const ull* kr = (const ull*)&Ks[mm*16];
            ull sp = 0ULL;
            #pragma unroll
            for (int k=0;k<8;k++) fma2(sp, q2[k], kr[k]);
            float2 sf = unpack2(sp);
            float s = (sf.x + sf.y)*0.25f;
            if (s > mx) {
                float cr = __expf(mx - s);
                ss *= cr;
                ull cp = pack2(cr, cr);
                #pragma unroll
                for (int k=0;k<32;k++) mul2(o2[k], cp);
                mx = s;
            }
            float w = __expf(s - mx);
            ss += w;
            ull wp = pack2(w, w);
            const ulonglong2* vr = (const ulonglong2*)&Vs[mm*64];
            #pragma unroll
            for (int k=0;k<16;k++) {
                ulonglong2 vv = vr[k];
                fma2(o2[2*k],   vv.x, wp);
                fma2(o2[2*k+1], vv.y, wp);
            }
        }
    }
    g_pmx[seg*(BB*NN) + bn] = mx;
    g_pss[seg*(BB*NN) + bn] = ss;
    float inv = 1.f/ss;
    float2* dst = (float2*)&g_pop[(size_t)seg*BB*NN*64 + (size_t)bn*64];
    #pragma unroll
    for (int k=0;k<32;k++) {
        float2 f = unpack2(o2[k]);
        f.x *= inv; f.y *= inv;
        dst[k] = f;
    }
}

// merge 4 attn segments; off = relu(tw@(px-po)+tb); g_po := px + off
__global__ void k_trans(const float* __restrict__ tw, const float* __restrict__ tb) {
    extern __shared__ float sm[];
    float* D  = sm;          // 4224 (stride 66)
    float* Wn = sm + 4224;   // 8192
    __shared__ float Aw[320];
    int blk = blockIdx.x;
    int b = blk>>6;
    int n0 = (blk&63)*64;
    int t = threadIdx.x;
    if (t < 64) {
        int bn = b*NN + n0 + t;
        float m[4], s[4];
        float mm = -3e30f;
        #pragma unroll
        for (int sg=0; sg<4; sg++) {
            m[sg] = g_pmx[sg*(BB*NN)+bn];
            s[sg] = g_pss[sg*(BB*NN)+bn];
            mm = fmaxf(mm, m[sg]);
        }
        float den = 0.f;
        #pragma unroll
        for (int sg=0; sg<4; sg++) {
            float a = s[sg]*__expf(m[sg]-mm);
            Aw[t*5+sg] = a;
            den += a;
        }
        Aw[t*5+4] = 1.f/den;
    }
    STAGE_W(Wn, tw[jj_*64+ci_])
    __syncthreads();
    for (int i=t; i<4096; i+=256){
        int pt=i>>6, c=i&63;
        int bn = b*NN + n0 + pt;
        float po = 0.f;
        #pragma unroll
        for (int sg=0; sg<4; sg++)
            po += g_pop[(size_t)sg*BB*NN*64 + (size_t)bn*64 + c]*Aw[pt*5+sg];
        po *= Aw[pt*5+4];
        D[pt*WS+c] = g_px[bn*64+c] - po;
    }
    __syncthreads();
    int r = t>>4, q = t&15;
    ull acc[4][2];
    {
        ull b0 = pack2(tb[q*4],   tb[q*4+1]);
        ull b1 = pack2(tb[q*4+2], tb[q*4+3]);
        #pragma unroll
        for (int i=0;i<4;i++){ acc[i][0]=b0; acc[i][1]=b1; }
    }
    GEMM_TW(acc, D, Wn)
    #pragma unroll
    for (int i=0;i<4;i++)
        #pragma unroll
        for (int jp=0;jp<2;jp++) {
            float2 f = unpack2(acc[i][jp]);
            int gi = (b*NN+n0+r*4+i)*64 + q*4 + 2*jp;
            g_po[gi]   = g_px[gi]   + fmaxf(f.x, 0.f);
            g_po[gi+1] = g_px[gi+1] + fmaxf(f.y, 0.f);
        }
}

// devoxelize(trilinear) * SE + point branch -> d_out
__global__ void k_out(float* __restrict__ out) {
    __shared__ int idxS[512];
    __shared__ float wS[512];
    __shared__ float obuf[4160];
    int blk = blockIdx.x;
    int b = blk>>6;
    int n0 = (blk&63)*64;
    int t = threadIdx.x;
    if (t < 64) {
        int n = n0 + t;
        const float* ncb = g_nc + b*3*NN;
        float f0=ncb[n], f1=ncb[NN+n], f2=ncb[2*NN+n];
        float fl0=floorf(f0), fl1=floorf(f1), fl2=floorf(f2);
        int x0=(int)fl0, y0=(int)fl1, z0=(int)fl2;
        float a0=f0-fl0, a1=f1-fl1, a2=f2-fl2;
        for (int k=0;k<8;k++){
            int dx=k>>2, dy=(k>>1)&1, dz=k&1;
            int xi=min(x0+dx,31), yi=min(y0+dy,31), zi=min(z0+dz,31);
            idxS[t*8+k] = (xi*32+yi)*32+zi;
            wS[t*8+k] = (dx?a0:1.f-a0)*(dy?a1:1.f-a1)*(dz?a2:1.f-a2);
        }
    }
    __syncthreads();
    int c = t&63, sub = t>>6;
    float sec = g_se[b*64+c];
    for (int nq=0; nq<16; nq++) {
        int nl = nq*4 + sub;
        float v = 0.f;
        #pragma unroll
        for (int k=0;k<8;k++)
            v += g_x[(b*VV + idxS[nl*8+k])*64 + c]*wS[nl*8+k];
        obuf[nl*65 + c] = v*sec + g_po[(b*NN+n0+nl)*64+c];
    }
    __syncthreads();
    for (int i=t; i<4096; i+=256) {
        int cc = i>>6, nl = i&63;
        out[(b*64+cc)*NN + n0+nl] = obuf[nl*65+cc];
    }
}

__global__ void k_copy(float* __restrict__ out, const float* __restrict__ coords) {
    int i = blockIdx.x*256 + threadIdx.x;
    if (i < BB*3*NN) out[BB*64*NN + i] = coords[i];
}

extern "C" void kernel_launch(void* const* d_in, const int* in_sizes, int n_in,
                              void* d_out, int out_size) {
    const float* feat   = (const float*)d_in[0];
    const float* coords = (const float*)d_in[1];
    const float* convw  = (const float*)d_in[2];
    const float* convb  = (const float*)d_in[3];
    const float* ln1g   = (const float*)d_in[4];
    const float* ln1b   = (const float*)d_in[5];
    const float* qkvw   = (const float*)d_in[6];
    const float* qkvb   = (const float*)d_in[7];
    const float* projw  = (const float*)d_in[8];
    const float* projb  = (const float*)d_in[9];
    const float* ln2g   = (const float*)d_in[10];
    const float* ln2b   = (const float*)d_in[11];
    const float* mw1    = (const float*)d_in[12];
    const float* mb1    = (const float*)d_in[13];
    const float* mw2    = (const float*)d_in[14];
    const float* mb2    = (const float*)d_in[15];
    const float* sew1   = (const float*)d_in[16];
    const float* sew2   = (const float*)d_in[17];
    const float* ptw    = (const float*)d_in[18];
    const float* ptb    = (const float*)d_in[19];
    const float* qw     = (const float*)d_in[20];
    const float* kw     = (const float*)d_in[21];
    const float* vw     = (const float*)d_in[22];
    const float* tw     = (const float*)d_in[23];
    const float* tb     = (const float*)d_in[24];
    float* out = (float*)d_out;

    cudaFuncSetAttribute(k_conv,      cudaFuncAttributeMaxDynamicSharedMemorySize, 77616);
    cudaFuncSetAttribute(k_winattn,   cudaFuncAttributeMaxDynamicSharedMemorySize, 100352);
    cudaFuncSetAttribute(k_mlp,       cudaFuncAttributeMaxDynamicSharedMemorySize, 66560);
    cudaFuncSetAttribute(k_pointmaps, cudaFuncAttributeMaxDynamicSharedMemorySize, 49664);
    cudaFuncSetAttribute(k_trans,     cudaFuncAttributeMaxDynamicSharedMemorySize, 49664);

    k_initstats<<<8196, 256>>>(convw, coords);
    k_scatter<<<4096, 256>>>(feat);
    k_conv<<<1024, 256, 77616>>>(convb);
    k_winattn<<<2048, 256, 100352>>>(ln1g, ln1b, qkvw, qkvb, projw, projb); // launch #4 -> profiled
    k_mlp<<<2048, 256, 66560>>>(ln2g, ln2b, mw1, mb1, mw2, mb2);
    k_sereduce<<<128, 256>>>();
    k_se<<<1, 256>>>(sew1, sew2);
    k_pointmaps<<<256, 256, 49664>>>(feat, ptw, ptb, qw, kw, vw);
    k_pointattn<<<256, 256>>>();
    k_trans<<<256, 256, 49664>>>(tw, tb);
    k_out<<<256, 256>>>(out);
    if (out_size >= BB*64*NN + BB*3*NN)
        k_copy<<<192, 256>>>(out, coords);
}

// round 11
// speedup vs baseline: 1.0734x; 1.0248x over previous
#include <cuda_runtime.h>
#include <math.h>

#define BB 4
#define NN 4096
#define RR 32
#define VV (RR*RR*RR)

__device__ float g_grid[BB*VV*64];
__device__ float g_cnt[BB*VV];
__device__ float g_nc[BB*3*NN];
__device__ float g_x[BB*VV*64];
__device__ float g_wt[9*3*64*64];
__device__ float g_semean[BB*64];
__device__ float g_se[BB*64];
__device__ float g_px[BB*NN*64];
__device__ float g_pq[BB*NN*16];
__device__ float g_pk[BB*NN*16];
__device__ float g_pv[BB*NN*64];
__device__ float g_pop[4*BB*NN*64];
__device__ float g_po[BB*NN*64];
__device__ float g_pmx[4*BB*NN];
__device__ float g_pss[4*BB*NN];

typedef unsigned long long ull;

__device__ __forceinline__ ull pack2(float x, float y) {
    ull r; asm("mov.b64 %0, {%1, %2};" : "=l"(r) : "f"(x), "f"(y)); return r;
}
__device__ __forceinline__ float2 unpack2(ull v) {
    float2 f; asm("mov.b64 {%0, %1}, %2;" : "=f"(f.x), "=f"(f.y) : "l"(v)); return f;
}
__device__ __forceinline__ void fma2(ull &d, ull a, ull b) {
    asm("fma.rn.f32x2 %0, %1, %2, %0;" : "+l"(d) : "l"(a), "l"(b));
}
__device__ __forceinline__ void mul2(ull &d, ull a) {
    asm("mul.rn.f32x2 %0, %0, %1;" : "+l"(d) : "l"(a));
}

#define WS 66

// stage a 64x64 row-major weight matrix transposed into stride-68 smem
#define STAGE_W(WT, SRCROW) \
    for (int i_=threadIdx.x; i_<4096; i_+=256){ \
        int jj_=i_>>6, ci_=i_&63; \
        (WT)[ci_*68+jj_] = (SRCROW); \
    }

// GEMM microkernel: acc[i][jp] += A_row(r*4+i)[ci] * Wt[ci*68 + q*4 + 2*jp .. +1]
#define GEMM_TW(ACC, ABUF, WT) \
    for (int ci=0; ci<64; ci++) { \
        ull w01 = *(const ull*)&(WT)[ci*68 + q*4]; \
        ull w23 = *(const ull*)&(WT)[ci*68 + q*4 + 2]; \
        _Pragma("unroll") \
        for (int i=0;i<4;i++) { \
            float av = (ABUF)[(r*4+i)*WS+ci]; \
            ull ap = pack2(av,av); \
            fma2(ACC[i][0], ap, w01); \
            fma2(ACC[i][1], ap, w23); \
        } \
    }

// fused init (zero + conv weight transpose) + per-batch coord stats
__global__ void k_initstats(const float* __restrict__ w, const float* __restrict__ coords) {
    int blk = blockIdx.x;
    int t = threadIdx.x;
    if (blk < 8192) {
        int i = blk*256 + t;
        if (i < BB*VV*64/4) ((float4*)g_grid)[i] = make_float4(0.f,0.f,0.f,0.f);
        if (i < BB*VV)      g_cnt[i] = 0.f;
        if (i < BB*64)      g_semean[i] = 0.f;
        if (i < 9*3*64*64) {
            int co = i & 63;
            int ci = (i>>6) & 63;
            int kz = (i>>12) % 3;
            int g  = i / 12288;
            int dx = g/3, dy = g%3;
            g_wt[i] = w[(((co*64+ci)*3+dx)*3+dy)*3 + kz];
        }
        return;
    }
    int b = blk - 8192;
    __shared__ float red[256];
    __shared__ float mS[3], mxS;
    const float* cb = coords + b*3*NN;
    float s0=0.f, s1=0.f, s2=0.f;
    for (int n=t; n<NN; n+=256) { s0+=cb[n]; s1+=cb[NN+n]; s2+=cb[2*NN+n]; }
    float sv[3] = {s0,s1,s2};
    for (int d=0; d<3; d++) {
        red[t]=sv[d]; __syncthreads();
        for (int o=128;o;o>>=1){ if(t<o) red[t]+=red[t+o]; __syncthreads(); }
        if (t==0) mS[d] = red[0]*(1.f/NN);
        __syncthreads();
    }
    float m0=mS[0], m1=mS[1], m2=mS[2];
    float mx = 0.f;
    for (int n=t; n<NN; n+=256) {
        float dx=cb[n]-m0, dy=cb[NN+n]-m1, dz=cb[2*NN+n]-m2;
        mx = fmaxf(mx, dx*dx+dy*dy+dz*dz);
    }
    red[t]=mx; __syncthreads();
    for (int o=128;o;o>>=1){ if(t<o) red[t]=fmaxf(red[t],red[t+o]); __syncthreads(); }
    if (t==0) mxS = sqrtf(red[0]);
    __syncthreads();
    float inv = 1.f/(2.f*mxS);
    float* ncb = g_nc + b*3*NN;
    for (int n=t; n<NN; n+=256) {
        float v0 = ((cb[n]      -m0)*inv + 0.5f)*RR;
        float v1 = ((cb[NN+n]   -m1)*inv + 0.5f)*RR;
        float v2 = ((cb[2*NN+n] -m2)*inv + 0.5f)*RR;
        ncb[n]      = fminf(fmaxf(v0,0.f), 31.f);
        ncb[NN+n]   = fminf(fmaxf(v1,0.f), 31.f);
        ncb[2*NN+n] = fminf(fmaxf(v2,0.f), 31.f);
    }
}

__global__ void k_scatter(const float* __restrict__ feat) {
    int i = blockIdx.x*256 + threadIdx.x;
    const int PN = BB*NN;
    if (i >= 64*PN) return;
    int c = i / PN;
    int r = i % PN;
    int b = r / NN, n = r % NN;
    const float* ncb = g_nc + b*3*NN;
    int vx = (int)rintf(ncb[n]);
    int vy = (int)rintf(ncb[NN+n]);
    int vz = (int)rintf(ncb[2*NN+n]);
    int v = (vx*RR+vy)*RR+vz;
    if (c==0) atomicAdd(&g_cnt[b*VV+v], 1.f);
    atomicAdd(&g_grid[(b*VV+v)*64 + c], feat[(b*64+c)*NN + n]);
}

// 3x3x3 conv + bias + relu (round-7/8 best)
__global__ void __launch_bounds__(256) k_conv(const float* __restrict__ bias) {
    extern __shared__ float sm[];
    float* sLine = sm;
    float* sW    = sm + 13056;
    float* sCnt  = sm + 19200;
    int blk = blockIdx.x;
    int yg = blk & 7;
    int x  = (blk>>3) & 31;
    int b  = blk >> 8;
    int y0 = yg*4;
    int t  = threadIdx.x;
    int coq = t & 15;
    int yi  = (t >> 4) & 3;
    int zq  = t >> 6;
    ull acc[2][8];
    #pragma unroll
    for (int p=0; p<2; p++)
        #pragma unroll
        for (int z=0; z<8; z++) acc[p][z]=0ULL;

    for (int dx=0; dx<3; dx++) {
        __syncthreads();
        int xx = x + dx - 1;
        bool vx = (xx>=0 && xx<32);
        if (t < 204) {
            int yy = t/34, zz = t%34;
            int y = y0 - 1 + yy, z = zz - 1;
            float c = 1.f;
            if (vx && y>=0 && y<32 && z>=0 && z<32)
                c = fmaxf(g_cnt[b*VV + (xx*32+y)*32 + z], 1.f);
            sCnt[t] = __fdividef(1.f, c);
        }
        __syncthreads();
        for (int i=t; i<13056; i+=256) {
            int ci = i & 63;
            int zz = (i>>6) % 34;
            int yy = i / 2176;
            int y = y0 - 1 + yy, z = zz - 1;
            float val = 0.f;
            if (vx && y>=0 && y<32 && z>=0 && z<32)
                val = g_grid[(b*VV + (xx*32+y)*32 + z)*64 + ci] * sCnt[yy*34+zz];
            sLine[i] = val;
        }
        for (int dy=0; dy<3; dy++) {
            const float* wsrc = g_wt + (dx*3+dy)*12288;
            for (int ch=0; ch<2; ch++) {
                __syncthreads();
                for (int i=t; i<6144; i+=256) {
                    int kz = i / 2048;
                    int rem = i % 2048;
                    sW[i] = wsrc[kz*4096 + ch*2048 + rem];
                }
                __syncthreads();
                const float* Lb = sLine + (yi+dy)*2176 + zq*512 + ch*32;
                for (int cil=0; cil<32; cil++) {
                    const float* wb = sW + cil*64 + coq*4;
                    ull w0a = *(const ull*)(wb);
                    ull w0b = *(const ull*)(wb+2);
                    ull w1a = *(const ull*)(wb+2048);
                    ull w1b = *(const ull*)(wb+2050);
                    ull w2a = *(const ull*)(wb+4096);
                    ull w2b = *(const ull*)(wb+4098);
                    const float* L = Lb + cil;
                    float l0 = L[0], l1 = L[64];
                    ull p0 = pack2(l0,l0), p1 = pack2(l1,l1);
                    #pragma unroll
                    for (int z=0; z<8; z++) {
                        float l2 = L[(z+2)*64];
                        ull p2 = pack2(l2,l2);
                        fma2(acc[0][z], w0a, p0); fma2(acc[1][z], w0b, p0);
                        fma2(acc[0][z], w1a, p1); fma2(acc[1][z], w1b, p1);
                        fma2(acc[0][z], w2a, p2); fma2(acc[1][z], w2b, p2);
                        p0=p1; p1=p2;
                    }
                }
            }
        }
    }
    float b0 = bias[coq*4], b1 = bias[coq*4+1], b2 = bias[coq*4+2], b3 = bias[coq*4+3];
    int ybase = b*VV + (x*32 + y0 + yi)*32 + zq*8;
    #pragma unroll
    for (int z=0; z<8; z++) {
        float2 fa = unpack2(acc[0][z]);
        float2 fb = unpack2(acc[1][z]);
        float4 o;
        o.x = fmaxf(fa.x + b0, 0.f);
        o.y = fmaxf(fa.y + b1, 0.f);
        o.z = fmaxf(fb.x + b2, 0.f);
        o.w = fmaxf(fb.y + b3, 0.f);
        *(float4*)&g_x[(ybase+z)*64 + coq*4] = o;
    }
}

// window attention; Q stored into Hs (LN buffer) => 3 buffers + Wt = 68KB => 3 blocks/SM
__global__ void k_winattn(const float* __restrict__ g1, const float* __restrict__ bb1,
                          const float* __restrict__ qkvw, const float* __restrict__ qkvb,
                          const float* __restrict__ pw, const float* __restrict__ pb) {
    extern __shared__ float sm[];
    float* Hs = sm;            // LN out -> Q -> attn out
    float* Ks = sm + 4224;
    float* Vs = sm + 8448;
    float* Wt = sm + 12672;    // 4352
    __shared__ int vmap[64];
    int blk = blockIdx.x;
    int b = blk >> 9;
    int rr = blk & 511;
    int wx = rr>>6, wy = (rr>>3)&7, wz = rr&7;
    int t = threadIdx.x;
    if (t < 64) {
        int ix = t>>4, iy = (t>>2)&3, iz = t&3;
        int v = ((wx*4+ix)*32 + (wy*4+iy))*32 + (wz*4+iz);
        vmap[t] = v;
        const float* row = g_x + (b*VV + v)*64;
        float mean=0.f, m2=0.f;
        for (int c=0;c<64;c++){ float xv=row[c]; mean+=xv; m2+=xv*xv; }
        mean *= 0.015625f;
        m2 = m2*0.015625f - mean*mean;
        float rs = rsqrtf(m2 + 1e-5f);
        for (int c=0;c<64;c++) Hs[t*WS+c] = (row[c]-mean)*rs*g1[c] + bb1[c];
    }
    int r = t>>4, q = t&15;
    // K then V (distinct dst buffers, Hs stays live)
    for (int cc=1; cc<3; cc++) {
        __syncthreads();
        STAGE_W(Wt, qkvw[(cc*64+jj_)*64+ci_])
        __syncthreads();
        ull acc[4][2];
        {
            ull b0 = pack2(qkvb[cc*64+q*4],   qkvb[cc*64+q*4+1]);
            ull b1 = pack2(qkvb[cc*64+q*4+2], qkvb[cc*64+q*4+3]);
            #pragma unroll
            for (int i=0;i<4;i++){ acc[i][0]=b0; acc[i][1]=b1; }
        }
        GEMM_TW(acc, Hs, Wt)
        float* dst = (cc==1)?Ks:Vs;
        #pragma unroll
        for (int i=0;i<4;i++)
            #pragma unroll
            for (int jp=0;jp<2;jp++) {
                float2 f = unpack2(acc[i][jp]);
                *(float2*)&dst[(r*4+i)*WS + q*4 + 2*jp] = f;
            }
    }
    // Q last: results in regs, sync, overwrite Hs
    __syncthreads();
    STAGE_W(Wt, qkvw[jj_*64+ci_])
    __syncthreads();
    {
        ull acc[4][2];
        ull b0 = pack2(qkvb[q*4],   qkvb[q*4+1]);
        ull b1 = pack2(qkvb[q*4+2], qkvb[q*4+3]);
        #pragma unroll
        for (int i=0;i<4;i++){ acc[i][0]=b0; acc[i][1]=b1; }
        GEMM_TW(acc, Hs, Wt)
        __syncthreads();   // all Hs reads complete before overwrite
        #pragma unroll
        for (int i=0;i<4;i++)
            #pragma unroll
            for (int jp=0;jp<2;jp++) {
                float2 f = unpack2(acc[i][jp]);
                *(float2*)&Hs[(r*4+i)*WS + q*4 + 2*jp] = f;
            }
    }
    __syncthreads();
    {   // attention: thread = (tok, head); q from Hs, out to same Hs cells
        int tok = t&63, h = t>>6;
        ull q2[8], o2[8];
        const ull* qrow = (const ull*)&Hs[tok*WS + h*16];
        #pragma unroll
        for (int k=0;k<8;k++){ q2[k]=qrow[k]; o2[k]=0ULL; }
        float mx = -3e30f, ss = 0.f;
        for (int m=0; m<64; m++) {
            const ull* kr = (const ull*)&Ks[m*WS + h*16];
            ull sp = 0ULL;
            #pragma unroll
            for (int k=0;k<8;k++) fma2(sp, q2[k], kr[k]);
            float2 sf = unpack2(sp);
            float s = (sf.x + sf.y)*0.25f;
            if (s > mx) {
                float cr = __expf(mx - s);
                ss *= cr;
                ull cp = pack2(cr,cr);
                #pragma unroll
                for (int k=0;k<8;k++) mul2(o2[k], cp);
                mx = s;
            }
            float wv = __expf(s - mx);
            ss += wv;
            ull wp = pack2(wv,wv);
            const ull* vr = (const ull*)&Vs[m*WS + h*16];
            #pragma unroll
            for (int k=0;k<8;k++) fma2(o2[k], vr[k], wp);
        }
        float inv = 1.f/ss;
        #pragma unroll
        for (int k=0;k<8;k++) {
            float2 f = unpack2(o2[k]);
            Hs[tok*WS + h*16 + 2*k]   = f.x*inv;
            Hs[tok*WS + h*16 + 2*k+1] = f.y*inv;
        }
    }
    __syncthreads();
    STAGE_W(Wt, pw[jj_*64+ci_])
    __syncthreads();
    {
        ull acc[4][2];
        ull b0 = pack2(pb[q*4],   pb[q*4+1]);
        ull b1 = pack2(pb[q*4+2], pb[q*4+3]);
        #pragma unroll
        for (int i=0;i<4;i++){ acc[i][0]=b0; acc[i][1]=b1; }
        GEMM_TW(acc, Hs, Wt)
        #pragma unroll
        for (int i=0;i<4;i++)
            #pragma unroll
            for (int jp=0;jp<2;jp++) {
                float2 f = unpack2(acc[i][jp]);
                int gi = (b*VV + vmap[r*4+i])*64 + q*4 + 2*jp;
                g_x[gi]   += f.x;
                g_x[gi+1] += f.y;
            }
    }
}

// LN2 + MLP(gelu-tanh via exp) + residual; 64 tokens / block (round-8)
__global__ void k_mlp(const float* __restrict__ g2, const float* __restrict__ b2g,
                      const float* __restrict__ w1, const float* __restrict__ mb1,
                      const float* __restrict__ w2, const float* __restrict__ mb2) {
    extern __shared__ float sm[];
    float* Aa = sm;            // stride 66
    float* Hc = sm + 4224;     // stride 66
    float* Wt = sm + 8448;     // 4352
    int t = threadIdx.x;
    int gt0 = blockIdx.x*64;
    if (t < 64) {
        const float* row = g_x + (gt0+t)*64;
        float mean=0.f, m2=0.f;
        for (int c=0;c<64;c++){ float xv=row[c]; mean+=xv; m2+=xv*xv; }
        mean *= 0.015625f;
        m2 = m2*0.015625f - mean*mean;
        float rs = rsqrtf(m2 + 1e-5f);
        for (int c=0;c<64;c++) Aa[t*WS+c] = (row[c]-mean)*rs*g2[c] + b2g[c];
    }
    int r = t>>4, q = t&15;
    ull o2[4][2];
    {
        ull b0 = pack2(mb2[q*4],   mb2[q*4+1]);
        ull b1 = pack2(mb2[q*4+2], mb2[q*4+3]);
        #pragma unroll
        for (int i=0;i<4;i++){ o2[i][0]=b0; o2[i][1]=b1; }
    }
    for (int ch=0; ch<4; ch++) {
        __syncthreads();
        STAGE_W(Wt, w1[(ch*64+jj_)*64+ci_])
        __syncthreads();
        ull h2[4][2];
        {
            ull b0 = pack2(mb1[ch*64+q*4],   mb1[ch*64+q*4+1]);
            ull b1 = pack2(mb1[ch*64+q*4+2], mb1[ch*64+q*4+3]);
            #pragma unroll
            for (int i=0;i<4;i++){ h2[i][0]=b0; h2[i][1]=b1; }
        }
        GEMM_TW(h2, Aa, Wt)
        __syncthreads();
        #pragma unroll
        for (int i=0;i<4;i++)
            #pragma unroll
            for (int jp=0;jp<2;jp++) {
                float2 f = unpack2(h2[i][jp]);
                float u0 = 1.5957691216f*(f.x + 0.044715f*f.x*f.x*f.x);
                float u1 = 1.5957691216f*(f.y + 0.044715f*f.y*f.y*f.y);
                float t0 = 1.f - __fdividef(2.f, 1.f + __expf(u0));
                float t1 = 1.f - __fdividef(2.f, 1.f + __expf(u1));
                float2 g;
                g.x = 0.5f*f.x*(1.f + t0);
                g.y = 0.5f*f.y*(1.f + t1);
                *(float2*)&Hc[(r*4+i)*WS + q*4 + 2*jp] = g;
            }
        __syncthreads();
        STAGE_W(Wt, w2[jj_*256 + ch*64 + ci_])
        __syncthreads();
        GEMM_TW(o2, Hc, Wt)
    }
    #pragma unroll
    for (int i=0;i<4;i++)
        #pragma unroll
        for (int jp=0;jp<2;jp++) {
            float2 f = unpack2(o2[i][jp]);
            int gi = (gt0 + r*4+i)*64 + q*4 + 2*jp;
            g_x[gi]   += f.x;
            g_x[gi+1] += f.y;
        }
}

__global__ void k_sereduce() {
    int blk = blockIdx.x;
    int b = blk>>5, chunk = blk&31;
    int t = threadIdx.x;
    const float* base = g_x + (b*VV + chunk*1024)*64;
    float s = 0.f;
    for (int i=t; i<65536; i+=256) s += base[i];
    __shared__ float red[256];
    red[t]=s; __syncthreads();
    if (t < 64) {
        float v = red[t]+red[t+64]+red[t+128]+red[t+192];
        atomicAdd(&g_semean[b*64 + t], v);
    }
}

__global__ void k_se(const float* __restrict__ w1, const float* __restrict__ w2) {
    int t = threadIdx.x;
    int b = t>>6, c = t&63;
    __shared__ float hid[4][8];
    if (c < 8) {
        float a = 0.f;
        for (int ci=0;ci<64;ci++) a += w1[c*64+ci]*g_semean[b*64+ci];
        a *= (1.f/VV);
        hid[b][c] = fmaxf(a, 0.f);
    }
    __syncthreads();
    float s = 0.f;
    for (int j=0;j<8;j++) s += w2[c*8+j]*hid[b][j];
    g_se[b*64+c] = 1.f/(1.f + __expf(-s));
}

__global__ void k_pointmaps(const float* __restrict__ feat, const float* __restrict__ pw,
                            const float* __restrict__ pb, const float* __restrict__ qw,
                            const float* __restrict__ kw, const float* __restrict__ vw) {
    __shared__ float F[4224];     // stride 66
    __shared__ float Wt[4352];
    int blk = blockIdx.x;
    int b = blk>>6;
    int n0 = (blk&63)*64;
    int t = threadIdx.x;
    for (int i=t; i<4096; i+=256){ int pt=i&63, ci=i>>6; F[pt*WS+ci] = feat[(b*64+ci)*NN + n0+pt]; }
    STAGE_W(Wt, pw[jj_*64+ci_])
    __syncthreads();
    int r = t>>4, q = t&15;
    {
        ull acc[4][2];
        ull b0 = pack2(pb[q*4],   pb[q*4+1]);
        ull b1 = pack2(pb[q*4+2], pb[q*4+3]);
        #pragma unroll
        for (int i=0;i<4;i++){ acc[i][0]=b0; acc[i][1]=b1; }
        GEMM_TW(acc, F, Wt)
        __syncthreads();
        #pragma unroll
        for (int i=0;i<4;i++)
            #pragma unroll
            for (int jp=0;jp<2;jp++) {
                float2 f = unpack2(acc[i][jp]);
                f.x = fmaxf(f.x, 0.f);
                f.y = fmaxf(f.y, 0.f);
                *(float2*)&F[(r*4+i)*WS + q*4 + 2*jp] = f;
                *(float2*)&g_px[(b*NN + n0 + r*4+i)*64 + q*4 + 2*jp] = f;
            }
    }
    __syncthreads();
    for (int i=t; i<1024; i+=256) Wt[i] = qw[i];
    for (int i=t; i<1024; i+=256) Wt[1024+i] = kw[i];
    __syncthreads();
    {
        int pt = t&63, dh = t>>6;
        for (int dl=0; dl<4; dl++) {
            int d = dh*4 + dl;
            float aq=0.f, ak=0.f;
            for (int ci=0; ci<64; ci++) {
                float xv = F[pt*WS+ci];
                aq += xv*Wt[d*64+ci];
                ak += xv*Wt[1024 + d*64+ci];
            }
            g_pq[(b*NN+n0+pt)*16 + d] = aq;
            g_pk[(b*NN+n0+pt)*16 + d] = ak;
        }
    }
    __syncthreads();
    STAGE_W(Wt, vw[jj_*64+ci_])
    __syncthreads();
    {
        ull acc[4][2];
        #pragma unroll
        for (int i=0;i<4;i++){ acc[i][0]=0ULL; acc[i][1]=0ULL; }
        GEMM_TW(acc, F, Wt)
        #pragma unroll
        for (int i=0;i<4;i++)
            #pragma unroll
            for (int jp=0;jp<2;jp++) {
                float2 f = unpack2(acc[i][jp]);
                *(float2*)&g_pv[(b*NN + n0 + r*4+i)*64 + q*4 + 2*jp] = f;
            }
    }
}

// flash-style point attention, key-split into 4 segments of 1024
__global__ void k_pointattn() {
    __shared__ __align__(16) float Ks[2048];
    __shared__ __align__(16) float Vs[8192];
    int blk = blockIdx.x;
    int b = blk >> 6;
    int rem = blk & 63;
    int qg = rem >> 2;
    int seg = rem & 3;
    int t = threadIdx.x;
    int n = qg*256 + t;
    int bn = b*NN + n;
    ull q2[8];
    {
        const ull* qp = (const ull*)&g_pq[bn*16];
        #pragma unroll
        for (int k=0;k<8;k++) q2[k] = qp[k];
    }
    ull o2[32];
    #pragma unroll
    for (int k=0;k<32;k++) o2[k]=0ULL;
    float mx=-3e30f, ss=0.f;
    int m0base = seg*1024;
    for (int tile=0; tile<8; tile++) {
        int m0 = m0base + tile*128;
        __syncthreads();
        const float4* ksrc = (const float4*)&g_pk[(b*NN+m0)*16];
        float4* kdst = (float4*)Ks;
        for (int i=t; i<512; i+=256) kdst[i] = ksrc[i];
        const float4* vsrc = (const float4*)&g_pv[(b*NN+m0)*64];
        float4* vdst = (float4*)Vs;
        for (int i=t; i<2048; i+=256) vdst[i] = vsrc[i];
        __syncthreads();
        for (int mm=0; mm<128; mm++) {
            const ull* kr = (const ull*)&Ks[mm*16];
            ull sp = 0ULL;
            #pragma unroll
            for (int k=0;k<8;k++) fma2(sp, q2[k], kr[k]);
            float2 sf = unpack2(sp);
            float s = (sf.x + sf.y)*0.25f;
            if (s > mx) {
                float cr = __expf(mx - s);
                ss *= cr;
                ull cp = pack2(cr, cr);
                #pragma unroll
                for (int k=0;k<32;k++) mul2(o2[k], cp);
                mx = s;
            }
            float w = __expf(s - mx);
            ss += w;
            ull wp = pack2(w, w);
            const ulonglong2* vr = (const ulonglong2*)&Vs[mm*64];
            #pragma unroll
            for (int k=0;k<16;k++) {
                ulonglong2 vv = vr[k];
                fma2(o2[2*k],   vv.x, wp);
                fma2(o2[2*k+1], vv.y, wp);
            }
        }
    }
    g_pmx[seg*(BB*NN) + bn] = mx;
    g_pss[seg*(BB*NN) + bn] = ss;
    float inv = 1.f/ss;
    float2* dst = (float2*)&g_pop[(size_t)seg*BB*NN*64 + (size_t)bn*64];
    #pragma unroll
    for (int k=0;k<32;k++) {
        float2 f = unpack2(o2[k]);
        f.x *= inv; f.y *= inv;
        dst[k] = f;
    }
}

// merge 4 attn segments; off = relu(tw@(px-po)+tb); g_po := px + off
__global__ void k_trans(const float* __restrict__ tw, const float* __restrict__ tb) {
    __shared__ float D[4224];     // stride 66
    __shared__ float Wt[4352];
    __shared__ float Aw[320];
    int blk = blockIdx.x;
    int b = blk>>6;
    int n0 = (blk&63)*64;
    int t = threadIdx.x;
    if (t < 64) {
        int bn = b*NN + n0 + t;
        float m[4], s[4];
        float mm = -3e30f;
        #pragma unroll
        for (int sg=0; sg<4; sg++) {
            m[sg] = g_pmx[sg*(BB*NN)+bn];
            s[sg] = g_pss[sg*(BB*NN)+bn];
            mm = fmaxf(mm, m[sg]);
        }
        float den = 0.f;
        #pragma unroll
        for (int sg=0; sg<4; sg++) {
            float a = s[sg]*__expf(m[sg]-mm);
            Aw[t*5+sg] = a;
            den += a;
        }
        Aw[t*5+4] = 1.f/den;
    }
    STAGE_W(Wt, tw[jj_*64+ci_])
    __syncthreads();
    for (int i=t; i<4096; i+=256){
        int pt=i>>6, c=i&63;
        int bn = b*NN + n0 + pt;
        float po = 0.f;
        #pragma unroll
        for (int sg=0; sg<4; sg++)
            po += g_pop[(size_t)sg*BB*NN*64 + (size_t)bn*64 + c]*Aw[pt*5+sg];
        po *= Aw[pt*5+4];
        D[pt*WS+c] = g_px[bn*64+c] - po;
    }
    __syncthreads();
    int r = t>>4, q = t&15;
    ull acc[4][2];
    {
        ull b0 = pack2(tb[q*4],   tb[q*4+1]);
        ull b1 = pack2(tb[q*4+2], tb[q*4+3]);
        #pragma unroll
        for (int i=0;i<4;i++){ acc[i][0]=b0; acc[i][1]=b1; }
    }
    GEMM_TW(acc, D, Wt)
    #pragma unroll
    for (int i=0;i<4;i++)
        #pragma unroll
        for (int jp=0;jp<2;jp++) {
            float2 f = unpack2(acc[i][jp]);
            int gi = (b*NN+n0+r*4+i)*64 + q*4 + 2*jp;
            g_po[gi]   = g_px[gi]   + fmaxf(f.x, 0.f);
            g_po[gi+1] = g_px[gi+1] + fmaxf(f.y, 0.f);
        }
}

// devoxelize(trilinear) * SE + point branch -> d_out
__global__ void k_out(float* __restrict__ out) {
    __shared__ int idxS[512];
    __shared__ float wS[512];
    __shared__ float obuf[4160];
    int blk = blockIdx.x;
    int b = blk>>6;
    int n0 = (blk&63)*64;
    int t = threadIdx.x;
    if (t < 64) {
        int n = n0 + t;
        const float* ncb = g_nc + b*3*NN;
        float f0=ncb[n], f1=ncb[NN+n], f2=ncb[2*NN+n];
        float fl0=floorf(f0), fl1=floorf(f1), fl2=floorf(f2);
        int x0=(int)fl0, y0=(int)fl1, z0=(int)fl2;
        float a0=f0-fl0, a1=f1-fl1, a2=f2-fl2;
        for (int k=0;k<8;k++){
            int dx=k>>2, dy=(k>>1)&1, dz=k&1;
            int xi=min(x0+dx,31), yi=min(y0+dy,31), zi=min(z0+dz,31);
            idxS[t*8+k] = (xi*32+yi)*32+zi;
            wS[t*8+k] = (dx?a0:1.f-a0)*(dy?a1:1.f-a1)*(dz?a2:1.f-a2);
        }
    }
    __syncthreads();
    int c = t&63, sub = t>>6;
    float sec = g_se[b*64+c];
    for (int nq=0; nq<16; nq++) {
        int nl = nq*4 + sub;
        float v = 0.f;
        #pragma unroll
        for (int k=0;k<8;k++)
            v += g_x[(b*VV + idxS[nl*8+k])*64 + c]*wS[nl*8+k];
        obuf[nl*65 + c] = v*sec + g_po[(b*NN+n0+nl)*64+c];
    }
    __syncthreads();
    for (int i=t; i<4096; i+=256) {
        int cc = i>>6, nl = i&63;
        out[(b*64+cc)*NN + n0+nl] = obuf[nl*65+cc];
    }
}

__global__ void k_copy(float* __restrict__ out, const float* __restrict__ coords) {
    int i = blockIdx.x*256 + threadIdx.x;
    if (i < BB*3*NN) out[BB*64*NN + i] = coords[i];
}

extern "C" void kernel_launch(void* const* d_in, const int* in_sizes, int n_in,
                              void* d_out, int out_size) {
    const float* feat   = (const float*)d_in[0];
    const float* coords = (const float*)d_in[1];
    const float* convw  = (const float*)d_in[2];
    const float* convb  = (const float*)d_in[3];
    const float* ln1g   = (const float*)d_in[4];
    const float* ln1b   = (const float*)d_in[5];
    const float* qkvw   = (const float*)d_in[6];
    const float* qkvb   = (const float*)d_in[7];
    const float* projw  = (const float*)d_in[8];
    const float* projb  = (const float*)d_in[9];
    const float* ln2g   = (const float*)d_in[10];
    const float* ln2b   = (const float*)d_in[11];
    const float* mw1    = (const float*)d_in[12];
    const float* mb1    = (const float*)d_in[13];
    const float* mw2    = (const float*)d_in[14];
    const float* mb2    = (const float*)d_in[15];
    const float* sew1   = (const float*)d_in[16];
    const float* sew2   = (const float*)d_in[17];
    const float* ptw    = (const float*)d_in[18];
    const float* ptb    = (const float*)d_in[19];
    const float* qw     = (const float*)d_in[20];
    const float* kw     = (const float*)d_in[21];
    const float* vw     = (const float*)d_in[22];
    const float* tw     = (const float*)d_in[23];
    const float* tb     = (const float*)d_in[24];
    float* out = (float*)d_out;

    cudaFuncSetAttribute(k_conv,    cudaFuncAttributeMaxDynamicSharedMemorySize, 77616);
    cudaFuncSetAttribute(k_winattn, cudaFuncAttributeMaxDynamicSharedMemorySize, 68096);
    cudaFuncSetAttribute(k_mlp,     cudaFuncAttributeMaxDynamicSharedMemorySize, 51200);

    k_initstats<<<8196, 256>>>(convw, coords);
    k_scatter<<<4096, 256>>>(feat);
    k_conv<<<1024, 256, 77616>>>(convb);
    k_winattn<<<2048, 256, 68096>>>(ln1g, ln1b, qkvw, qkvb, projw, projb); // launch #4 -> profiled
    k_mlp<<<2048, 256, 51200>>>(ln2g, ln2b, mw1, mb1, mw2, mb2);
    k_sereduce<<<128, 256>>>();
    k_se<<<1, 256>>>(sew1, sew2);
    k_pointmaps<<<256, 256>>>(feat, ptw, ptb, qw, kw, vw);
    k_pointattn<<<256, 256>>>();
    k_trans<<<256, 256>>>(tw, tb);
    k_out<<<256, 256>>>(out);
    if (out_size >= BB*64*NN + BB*3*NN)
        k_copy<<<192, 256>>>(out, coords);
}

// round 12
// speedup vs baseline: 1.0795x; 1.0058x over previous
#include <cuda_runtime.h>
#include <math.h>

#define BB 4
#define NN 4096
#define RR 32
#define VV (RR*RR*RR)

__device__ float g_grid[BB*VV*64];
__device__ float g_cnt[BB*VV];
__device__ float g_nc[BB*3*NN];
__device__ float g_x[BB*VV*64];
__device__ float g_wt[9*3*64*64];
__device__ float g_semean[BB*64];
__device__ float g_se[BB*64];
__device__ float g_px[BB*NN*64];
__device__ float g_pq[BB*NN*16];
__device__ float g_pk[BB*NN*16];
__device__ float g_pv[BB*NN*64];
__device__ float g_pop[4*BB*NN*64];
__device__ float g_po[BB*NN*64];
__device__ float g_pmx[4*BB*NN];
__device__ float g_pss[4*BB*NN];

typedef unsigned long long ull;

__device__ __forceinline__ ull pack2(float x, float y) {
    ull r; asm("mov.b64 %0, {%1, %2};" : "=l"(r) : "f"(x), "f"(y)); return r;
}
__device__ __forceinline__ float2 unpack2(ull v) {
    float2 f; asm("mov.b64 {%0, %1}, %2;" : "=f"(f.x), "=f"(f.y) : "l"(v)); return f;
}
__device__ __forceinline__ void fma2(ull &d, ull a, ull b) {
    asm("fma.rn.f32x2 %0, %1, %2, %0;" : "+l"(d) : "l"(a), "l"(b));
}
__device__ __forceinline__ void mul2(ull &d, ull a) {
    asm("mul.rn.f32x2 %0, %0, %1;" : "+l"(d) : "l"(a));
}

#define WS 66

// stage a 64x64 row-major weight matrix transposed into stride-68 smem
#define STAGE_W(WT, SRCROW) \
    for (int i_=threadIdx.x; i_<4096; i_+=256){ \
        int jj_=i_>>6, ci_=i_&63; \
        (WT)[ci_*68+jj_] = (SRCROW); \
    }

// GEMM microkernel over ci-pairs: weights via conflict-free LDS.128,
// activations via broadcast LDS.64. Accumulation order identical to
// sequential-ci version (even ci then odd ci).
#define GEMM_TW(ACC, ABUF, WT) \
    for (int cp=0; cp<32; cp++) { \
        float4 we_ = *(const float4*)&(WT)[(2*cp)*68 + q*4]; \
        float4 wo_ = *(const float4*)&(WT)[(2*cp+1)*68 + q*4]; \
        ull we01_ = pack2(we_.x, we_.y), we23_ = pack2(we_.z, we_.w); \
        ull wo01_ = pack2(wo_.x, wo_.y), wo23_ = pack2(wo_.z, wo_.w); \
        _Pragma("unroll") \
        for (int i=0;i<4;i++) { \
            float2 a_ = *(const float2*)&(ABUF)[(r*4+i)*WS + 2*cp]; \
            ull ae_ = pack2(a_.x, a_.x); \
            ull ao_ = pack2(a_.y, a_.y); \
            fma2(ACC[i][0], ae_, we01_); \
            fma2(ACC[i][1], ae_, we23_); \
            fma2(ACC[i][0], ao_, wo01_); \
            fma2(ACC[i][1], ao_, wo23_); \
        } \
    }

// fused init (zero + conv weight transpose) + per-batch coord stats
__global__ void k_initstats(const float* __restrict__ w, const float* __restrict__ coords) {
    int blk = blockIdx.x;
    int t = threadIdx.x;
    if (blk < 8192) {
        int i = blk*256 + t;
        if (i < BB*VV*64/4) ((float4*)g_grid)[i] = make_float4(0.f,0.f,0.f,0.f);
        if (i < BB*VV)      g_cnt[i] = 0.f;
        if (i < BB*64)      g_semean[i] = 0.f;
        if (i < 9*3*64*64) {
            int co = i & 63;
            int ci = (i>>6) & 63;
            int kz = (i>>12) % 3;
            int g  = i / 12288;
            int dx = g/3, dy = g%3;
            g_wt[i] = w[(((co*64+ci)*3+dx)*3+dy)*3 + kz];
        }
        return;
    }
    int b = blk - 8192;
    __shared__ float red[256];
    __shared__ float mS[3], mxS;
    const float* cb = coords + b*3*NN;
    float s0=0.f, s1=0.f, s2=0.f;
    for (int n=t; n<NN; n+=256) { s0+=cb[n]; s1+=cb[NN+n]; s2+=cb[2*NN+n]; }
    float sv[3] = {s0,s1,s2};
    for (int d=0; d<3; d++) {
        red[t]=sv[d]; __syncthreads();
        for (int o=128;o;o>>=1){ if(t<o) red[t]+=red[t+o]; __syncthreads(); }
        if (t==0) mS[d] = red[0]*(1.f/NN);
        __syncthreads();
    }
    float m0=mS[0], m1=mS[1], m2=mS[2];
    float mx = 0.f;
    for (int n=t; n<NN; n+=256) {
        float dx=cb[n]-m0, dy=cb[NN+n]-m1, dz=cb[2*NN+n]-m2;
        mx = fmaxf(mx, dx*dx+dy*dy+dz*dz);
    }
    red[t]=mx; __syncthreads();
    for (int o=128;o;o>>=1){ if(t<o) red[t]=fmaxf(red[t],red[t+o]); __syncthreads(); }
    if (t==0) mxS = sqrtf(red[0]);
    __syncthreads();
    float inv = 1.f/(2.f*mxS);
    float* ncb = g_nc + b*3*NN;
    for (int n=t; n<NN; n+=256) {
        float v0 = ((cb[n]      -m0)*inv + 0.5f)*RR;
        float v1 = ((cb[NN+n]   -m1)*inv + 0.5f)*RR;
        float v2 = ((cb[2*NN+n] -m2)*inv + 0.5f)*RR;
        ncb[n]      = fminf(fmaxf(v0,0.f), 31.f);
        ncb[NN+n]   = fminf(fmaxf(v1,0.f), 31.f);
        ncb[2*NN+n] = fminf(fmaxf(v2,0.f), 31.f);
    }
}

__global__ void k_scatter(const float* __restrict__ feat) {
    int i = blockIdx.x*256 + threadIdx.x;
    const int PN = BB*NN;
    if (i >= 64*PN) return;
    int c = i / PN;
    int r = i % PN;
    int b = r / NN, n = r % NN;
    const float* ncb = g_nc + b*3*NN;
    int vx = (int)rintf(ncb[n]);
    int vy = (int)rintf(ncb[NN+n]);
    int vz = (int)rintf(ncb[2*NN+n]);
    int v = (vx*RR+vy)*RR+vz;
    if (c==0) atomicAdd(&g_cnt[b*VV+v], 1.f);
    atomicAdd(&g_grid[(b*VV+v)*64 + c], feat[(b*64+c)*NN + n]);
}

// 3x3x3 conv + bias + relu (round-7/8 best)
__global__ void __launch_bounds__(256) k_conv(const float* __restrict__ bias) {
    extern __shared__ float sm[];
    float* sLine = sm;
    float* sW    = sm + 13056;
    float* sCnt  = sm + 19200;
    int blk = blockIdx.x;
    int yg = blk & 7;
    int x  = (blk>>3) & 31;
    int b  = blk >> 8;
    int y0 = yg*4;
    int t  = threadIdx.x;
    int coq = t & 15;
    int yi  = (t >> 4) & 3;
    int zq  = t >> 6;
    ull acc[2][8];
    #pragma unroll
    for (int p=0; p<2; p++)
        #pragma unroll
        for (int z=0; z<8; z++) acc[p][z]=0ULL;

    for (int dx=0; dx<3; dx++) {
        __syncthreads();
        int xx = x + dx - 1;
        bool vx = (xx>=0 && xx<32);
        if (t < 204) {
            int yy = t/34, zz = t%34;
            int y = y0 - 1 + yy, z = zz - 1;
            float c = 1.f;
            if (vx && y>=0 && y<32 && z>=0 && z<32)
                c = fmaxf(g_cnt[b*VV + (xx*32+y)*32 + z], 1.f);
            sCnt[t] = __fdividef(1.f, c);
        }
        __syncthreads();
        for (int i=t; i<13056; i+=256) {
            int ci = i & 63;
            int zz = (i>>6) % 34;
            int yy = i / 2176;
            int y = y0 - 1 + yy, z = zz - 1;
            float val = 0.f;
            if (vx && y>=0 && y<32 && z>=0 && z<32)
                val = g_grid[(b*VV + (xx*32+y)*32 + z)*64 + ci] * sCnt[yy*34+zz];
            sLine[i] = val;
        }
        for (int dy=0; dy<3; dy++) {
            const float* wsrc = g_wt + (dx*3+dy)*12288;
            for (int ch=0; ch<2; ch++) {
                __syncthreads();
                for (int i=t; i<6144; i+=256) {
                    int kz = i / 2048;
                    int rem = i % 2048;
                    sW[i] = wsrc[kz*4096 + ch*2048 + rem];
                }
                __syncthreads();
                const float* Lb = sLine + (yi+dy)*2176 + zq*512 + ch*32;
                for (int cil=0; cil<32; cil++) {
                    const float* wb = sW + cil*64 + coq*4;
                    ull w0a = *(const ull*)(wb);
                    ull w0b = *(const ull*)(wb+2);
                    ull w1a = *(const ull*)(wb+2048);
                    ull w1b = *(const ull*)(wb+2050);
                    ull w2a = *(const ull*)(wb+4096);
                    ull w2b = *(const ull*)(wb+4098);
                    const float* L = Lb + cil;
                    float l0 = L[0], l1 = L[64];
                    ull p0 = pack2(l0,l0), p1 = pack2(l1,l1);
                    #pragma unroll
                    for (int z=0; z<8; z++) {
                        float l2 = L[(z+2)*64];
                        ull p2 = pack2(l2,l2);
                        fma2(acc[0][z], w0a, p0); fma2(acc[1][z], w0b, p0);
                        fma2(acc[0][z], w1a, p1); fma2(acc[1][z], w1b, p1);
                        fma2(acc[0][z], w2a, p2); fma2(acc[1][z], w2b, p2);
                        p0=p1; p1=p2;
                    }
                }
            }
        }
    }
    float b0 = bias[coq*4], b1 = bias[coq*4+1], b2 = bias[coq*4+2], b3 = bias[coq*4+3];
    int ybase = b*VV + (x*32 + y0 + yi)*32 + zq*8;
    #pragma unroll
    for (int z=0; z<8; z++) {
        float2 fa = unpack2(acc[0][z]);
        float2 fb = unpack2(acc[1][z]);
        float4 o;
        o.x = fmaxf(fa.x + b0, 0.f);
        o.y = fmaxf(fa.y + b1, 0.f);
        o.z = fmaxf(fb.x + b2, 0.f);
        o.w = fmaxf(fb.y + b3, 0.f);
        *(float4*)&g_x[(ybase+z)*64 + coq*4] = o;
    }
}

// window attention; Q stored into Hs (LN buffer) => 68KB => 3 blocks/SM
__global__ void k_winattn(const float* __restrict__ g1, const float* __restrict__ bb1,
                          const float* __restrict__ qkvw, const float* __restrict__ qkvb,
                          const float* __restrict__ pw, const float* __restrict__ pb) {
    extern __shared__ float sm[];
    float* Hs = sm;            // LN out -> Q -> attn out
    float* Ks = sm + 4224;
    float* Vs = sm + 8448;
    float* Wt = sm + 12672;    // 4352
    __shared__ int vmap[64];
    int blk = blockIdx.x;
    int b = blk >> 9;
    int rr = blk & 511;
    int wx = rr>>6, wy = (rr>>3)&7, wz = rr&7;
    int t = threadIdx.x;
    if (t < 64) {
        int ix = t>>4, iy = (t>>2)&3, iz = t&3;
        int v = ((wx*4+ix)*32 + (wy*4+iy))*32 + (wz*4+iz);
        vmap[t] = v;
        const float* row = g_x + (b*VV + v)*64;
        float mean=0.f, m2=0.f;
        for (int c=0;c<64;c++){ float xv=row[c]; mean+=xv; m2+=xv*xv; }
        mean *= 0.015625f;
        m2 = m2*0.015625f - mean*mean;
        float rs = rsqrtf(m2 + 1e-5f);
        for (int c=0;c<64;c++) Hs[t*WS+c] = (row[c]-mean)*rs*g1[c] + bb1[c];
    }
    int r = t>>4, q = t&15;
    // K then V (distinct dst buffers, Hs stays live)
    for (int cc=1; cc<3; cc++) {
        __syncthreads();
        STAGE_W(Wt, qkvw[(cc*64+jj_)*64+ci_])
        __syncthreads();
        ull acc[4][2];
        {
            ull b0 = pack2(qkvb[cc*64+q*4],   qkvb[cc*64+q*4+1]);
            ull b1 = pack2(qkvb[cc*64+q*4+2], qkvb[cc*64+q*4+3]);
            #pragma unroll
            for (int i=0;i<4;i++){ acc[i][0]=b0; acc[i][1]=b1; }
        }
        GEMM_TW(acc, Hs, Wt)
        float* dst = (cc==1)?Ks:Vs;
        #pragma unroll
        for (int i=0;i<4;i++)
            #pragma unroll
            for (int jp=0;jp<2;jp++) {
                float2 f = unpack2(acc[i][jp]);
                *(float2*)&dst[(r*4+i)*WS + q*4 + 2*jp] = f;
            }
    }
    // Q last: results in regs, sync, overwrite Hs
    __syncthreads();
    STAGE_W(Wt, qkvw[jj_*64+ci_])
    __syncthreads();
    {
        ull acc[4][2];
        ull b0 = pack2(qkvb[q*4],   qkvb[q*4+1]);
        ull b1 = pack2(qkvb[q*4+2], qkvb[q*4+3]);
        #pragma unroll
        for (int i=0;i<4;i++){ acc[i][0]=b0; acc[i][1]=b1; }
        GEMM_TW(acc, Hs, Wt)
        __syncthreads();   // all Hs reads complete before overwrite
        #pragma unroll
        for (int i=0;i<4;i++)
            #pragma unroll
            for (int jp=0;jp<2;jp++) {
                float2 f = unpack2(acc[i][jp]);
                *(float2*)&Hs[(r*4+i)*WS + q*4 + 2*jp] = f;
            }
    }
    __syncthreads();
    {   // attention: thread = (tok, head); q from Hs, out to same Hs cells
        int tok = t&63, h = t>>6;
        ull q2[8], o2[8];
        const ull* qrow = (const ull*)&Hs[tok*WS + h*16];
        #pragma unroll
        for (int k=0;k<8;k++){ q2[k]=qrow[k]; o2[k]=0ULL; }
        float mx = -3e30f, ss = 0.f;
        for (int m=0; m<64; m++) {
            const ull* kr = (const ull*)&Ks[m*WS + h*16];
            ull sp = 0ULL;
            #pragma unroll
            for (int k=0;k<8;k++) fma2(sp, q2[k], kr[k]);
            float2 sf = unpack2(sp);
            float s = (sf.x + sf.y)*0.25f;
            if (s > mx) {
                float cr = __expf(mx - s);
                ss *= cr;
                ull cp2 = pack2(cr,cr);
                #pragma unroll
                for (int k=0;k<8;k++) mul2(o2[k], cp2);
                mx = s;
            }
            float wv = __expf(s - mx);
            ss += wv;
            ull wp = pack2(wv,wv);
            const ull* vr = (const ull*)&Vs[m*WS + h*16];
            #pragma unroll
            for (int k=0;k<8;k++) fma2(o2[k], vr[k], wp);
        }
        float inv = 1.f/ss;
        #pragma unroll
        for (int k=0;k<8;k++) {
            float2 f = unpack2(o2[k]);
            Hs[tok*WS + h*16 + 2*k]   = f.x*inv;
            Hs[tok*WS + h*16 + 2*k+1] = f.y*inv;
        }
    }
    __syncthreads();
    STAGE_W(Wt, pw[jj_*64+ci_])
    __syncthreads();
    {
        ull acc[4][2];
        ull b0 = pack2(pb[q*4],   pb[q*4+1]);
        ull b1 = pack2(pb[q*4+2], pb[q*4+3]);
        #pragma unroll
        for (int i=0;i<4;i++){ acc[i][0]=b0; acc[i][1]=b1; }
        GEMM_TW(acc, Hs, Wt)
        #pragma unroll
        for (int i=0;i<4;i++)
            #pragma unroll
            for (int jp=0;jp<2;jp++) {
                float2 f = unpack2(acc[i][jp]);
                int gi = (b*VV + vmap[r*4+i])*64 + q*4 + 2*jp;
                g_x[gi]   += f.x;
                g_x[gi+1] += f.y;
            }
    }
}

// LN2 + MLP(gelu-tanh via exp) + residual; 64 tokens / block
__global__ void k_mlp(const float* __restrict__ g2, const float* __restrict__ b2g,
                      const float* __restrict__ w1, const float* __restrict__ mb1,
                      const float* __restrict__ w2, const float* __restrict__ mb2) {
    extern __shared__ float sm[];
    float* Aa = sm;            // stride 66
    float* Hc = sm + 4224;     // stride 66
    float* Wt = sm + 8448;     // 4352
    int t = threadIdx.x;
    int gt0 = blockIdx.x*64;
    if (t < 64) {
        const float* row = g_x + (gt0+t)*64;
        float mean=0.f, m2=0.f;
        for (int c=0;c<64;c++){ float xv=row[c]; mean+=xv; m2+=xv*xv; }
        mean *= 0.015625f;
        m2 = m2*0.015625f - mean*mean;
        float rs = rsqrtf(m2 + 1e-5f);
        for (int c=0;c<64;c++) Aa[t*WS+c] = (row[c]-mean)*rs*g2[c] + b2g[c];
    }
    int r = t>>4, q = t&15;
    ull o2[4][2];
    {
        ull b0 = pack2(mb2[q*4],   mb2[q*4+1]);
        ull b1 = pack2(mb2[q*4+2], mb2[q*4+3]);
        #pragma unroll
        for (int i=0;i<4;i++){ o2[i][0]=b0; o2[i][1]=b1; }
    }
    for (int ch=0; ch<4; ch++) {
        __syncthreads();
        STAGE_W(Wt, w1[(ch*64+jj_)*64+ci_])
        __syncthreads();
        ull h2[4][2];
        {
            ull b0 = pack2(mb1[ch*64+q*4],   mb1[ch*64+q*4+1]);
            ull b1 = pack2(mb1[ch*64+q*4+2], mb1[ch*64+q*4+3]);
            #pragma unroll
            for (int i=0;i<4;i++){ h2[i][0]=b0; h2[i][1]=b1; }
        }
        GEMM_TW(h2, Aa, Wt)
        __syncthreads();
        #pragma unroll
        for (int i=0;i<4;i++)
            #pragma unroll
            for (int jp=0;jp<2;jp++) {
                float2 f = unpack2(h2[i][jp]);
                float u0 = 1.5957691216f*(f.x + 0.044715f*f.x*f.x*f.x);
                float u1 = 1.5957691216f*(f.y + 0.044715f*f.y*f.y*f.y);
                float t0 = 1.f - __fdividef(2.f, 1.f + __expf(u0));
                float t1 = 1.f - __fdividef(2.f, 1.f + __expf(u1));
                float2 g;
                g.x = 0.5f*f.x*(1.f + t0);
                g.y = 0.5f*f.y*(1.f + t1);
                *(float2*)&Hc[(r*4+i)*WS + q*4 + 2*jp] = g;
            }
        __syncthreads();
        STAGE_W(Wt, w2[jj_*256 + ch*64 + ci_])
        __syncthreads();
        GEMM_TW(o2, Hc, Wt)
    }
    #pragma unroll
    for (int i=0;i<4;i++)
        #pragma unroll
        for (int jp=0;jp<2;jp++) {
            float2 f = unpack2(o2[i][jp]);
            int gi = (gt0 + r*4+i)*64 + q*4 + 2*jp;
            g_x[gi]   += f.x;
            g_x[gi+1] += f.y;
        }
}

__global__ void k_sereduce() {
    int blk = blockIdx.x;
    int b = blk>>5, chunk = blk&31;
    int t = threadIdx.x;
    const float* base = g_x + (b*VV + chunk*1024)*64;
    float s = 0.f;
    for (int i=t; i<65536; i+=256) s += base[i];
    __shared__ float red[256];
    red[t]=s; __syncthreads();
    if (t < 64) {
        float v = red[t]+red[t+64]+red[t+128]+red[t+192];
        atomicAdd(&g_semean[b*64 + t], v);
    }
}

__global__ void k_se(const float* __restrict__ w1, const float* __restrict__ w2) {
    int t = threadIdx.x;
    int b = t>>6, c = t&63;
    __shared__ float hid[4][8];
    if (c < 8) {
        float a = 0.f;
        for (int ci=0;ci<64;ci++) a += w1[c*64+ci]*g_semean[b*64+ci];
        a *= (1.f/VV);
        hid[b][c] = fmaxf(a, 0.f);
    }
    __syncthreads();
    float s = 0.f;
    for (int j=0;j<8;j++) s += w2[c*8+j]*hid[b][j];
    g_se[b*64+c] = 1.f/(1.f + __expf(-s));
}

__global__ void k_pointmaps(const float* __restrict__ feat, const float* __restrict__ pw,
                            const float* __restrict__ pb, const float* __restrict__ qw,
                            const float* __restrict__ kw, const float* __restrict__ vw) {
    __shared__ float F[4224];     // stride 66
    __shared__ float Wt[4352];
    int blk = blockIdx.x;
    int b = blk>>6;
    int n0 = (blk&63)*64;
    int t = threadIdx.x;
    for (int i=t; i<4096; i+=256){ int pt=i&63, ci=i>>6; F[pt*WS+ci] = feat[(b*64+ci)*NN + n0+pt]; }
    STAGE_W(Wt, pw[jj_*64+ci_])
    __syncthreads();
    int r = t>>4, q = t&15;
    {
        ull acc[4][2];
        ull b0 = pack2(pb[q*4],   pb[q*4+1]);
        ull b1 = pack2(pb[q*4+2], pb[q*4+3]);
        #pragma unroll
        for (int i=0;i<4;i++){ acc[i][0]=b0; acc[i][1]=b1; }
        GEMM_TW(acc, F, Wt)
        __syncthreads();
        #pragma unroll
        for (int i=0;i<4;i++)
            #pragma unroll
            for (int jp=0;jp<2;jp++) {
                float2 f = unpack2(acc[i][jp]);
                f.x = fmaxf(f.x, 0.f);
                f.y = fmaxf(f.y, 0.f);
                *(float2*)&F[(r*4+i)*WS + q*4 + 2*jp] = f;
                *(float2*)&g_px[(b*NN + n0 + r*4+i)*64 + q*4 + 2*jp] = f;
            }
    }
    __syncthreads();
    for (int i=t; i<1024; i+=256) Wt[i] = qw[i];
    for (int i=t; i<1024; i+=256) Wt[1024+i] = kw[i];
    __syncthreads();
    {
        int pt = t&63, dh = t>>6;
        for (int dl=0; dl<4; dl++) {
            int d = dh*4 + dl;
            float aq=0.f, ak=0.f;
            for (int ci=0; ci<64; ci++) {
                float xv = F[pt*WS+ci];
                aq += xv*Wt[d*64+ci];
                ak += xv*Wt[1024 + d*64+ci];
            }
            g_pq[(b*NN+n0+pt)*16 + d] = aq;
            g_pk[(b*NN+n0+pt)*16 + d] = ak;
        }
    }
    __syncthreads();
    STAGE_W(Wt, vw[jj_*64+ci_])
    __syncthreads();
    {
        ull acc[4][2];
        #pragma unroll
        for (int i=0;i<4;i++){ acc[i][0]=0ULL; acc[i][1]=0ULL; }
        GEMM_TW(acc, F, Wt)
        #pragma unroll
        for (int i=0;i<4;i++)
            #pragma unroll
            for (int jp=0;jp<2;jp++) {
                float2 f = unpack2(acc[i][jp]);
                *(float2*)&g_pv[(b*NN + n0 + r*4+i)*64 + q*4 + 2*jp] = f;
            }
    }
}

// flash-style point attention, key-split into 4 segments of 1024
__global__ void k_pointattn() {
    __shared__ __align__(16) float Ks[2048];
    __shared__ __align__(16) float Vs[8192];
    int blk = blockIdx.x;
    int b = blk >> 6;
    int rem = blk & 63;
    int qg = rem >> 2;
    int seg = rem & 3;
    int t = threadIdx.x;
    int n = qg*256 + t;
    int bn = b*NN + n;
    ull q2[8];
    {
        const ull* qp = (const ull*)&g_pq[bn*16];
        #pragma unroll
        for (int k=0;k<8;k++) q2[k] = qp[k];
    }
    ull o2[32];
    #pragma unroll
    for (int k=0;k<32;k++) o2[k]=0ULL;
    float mx=-3e30f, ss=0.f;
    int m0base = seg*1024;
    for (int tile=0; tile<8; tile++) {
        int m0 = m0base + tile*128;
        __syncthreads();
        const float4* ksrc = (const float4*)&g_pk[(b*NN+m0)*16];
        float4* kdst = (float4*)Ks;
        for (int i=t; i<512; i+=256) kdst[i] = ksrc[i];
        const float4* vsrc = (const float4*)&g_pv[(b*NN+m0)*64];
        float4* vdst = (float4*)Vs;
        for (int i=t; i<2048; i+=256) vdst[i] = vsrc[i];
        __syncthreads();
        for (int mm=0; mm<128; mm++) {
            const ull* kr = (const ull*)&Ks[mm*16];
            ull sp = 0ULL;
            #pragma unroll
            for (int k=0;k<8;k++) fma2(sp, q2[k], kr[k]);
            float2 sf = unpack2(sp);
            float s = (sf.x + sf.y)*0.25f;
            if (s > mx) {
                float cr = __expf(mx - s);
                ss *= cr;
                ull cp = pack2(cr, cr);
                #pragma unroll
                for (int k=0;k<32;k++) mul2(o2[k], cp);
                mx = s;
            }
            float w = __expf(s - mx);
            ss += w;
            ull wp = pack2(w, w);
            const ulonglong2* vr = (const ulonglong2*)&Vs[mm*64];
            #pragma unroll
            for (int k=0;k<16;k++) {
                ulonglong2 vv = vr[k];
                fma2(o2[2*k],   vv.x, wp);
                fma2(o2[2*k+1], vv.y, wp);
            }
        }
    }
    g_pmx[seg*(BB*NN) + bn] = mx;
    g_pss[seg*(BB*NN) + bn] = ss;
    float inv = 1.f/ss;
    float2* dst = (float2*)&g_pop[(size_t)seg*BB*NN*64 + (size_t)bn*64];
    #pragma unroll
    for (int k=0;k<32;k++) {
        float2 f = unpack2(o2[k]);
        f.x *= inv; f.y *= inv;
        dst[k] = f;
    }
}

// merge 4 attn segments; off = relu(tw@(px-po)+tb); g_po := px + off
__global__ void k_trans(const float* __restrict__ tw, const float* __restrict__ tb) {
    __shared__ float D[4224];     // stride 66
    __shared__ float Wt[4352];
    __shared__ float Aw[320];
    int blk = blockIdx.x;
    int b = blk>>6;
    int n0 = (blk&63)*64;
    int t = threadIdx.x;
    if (t < 64) {
        int bn = b*NN + n0 + t;
        float m[4], s[4];
        float mm = -3e30f;
        #pragma unroll
        for (int sg=0; sg<4; sg++) {
            m[sg] = g_pmx[sg*(BB*NN)+bn];
            s[sg] = g_pss[sg*(BB*NN)+bn];
            mm = fmaxf(mm, m[sg]);
        }
        float den = 0.f;
        #pragma unroll
        for (int sg=0; sg<4; sg++) {
            float a = s[sg]*__expf(m[sg]-mm);
            Aw[t*5+sg] = a;
            den += a;
        }
        Aw[t*5+4] = 1.f/den;
    }
    STAGE_W(Wt, tw[jj_*64+ci_])
    __syncthreads();
    for (int i=t; i<4096; i+=256){
        int pt=i>>6, c=i&63;
        int bn = b*NN + n0 + pt;
        float po = 0.f;
        #pragma unroll
        for (int sg=0; sg<4; sg++)
            po += g_pop[(size_t)sg*BB*NN*64 + (size_t)bn*64 + c]*Aw[pt*5+sg];
        po *= Aw[pt*5+4];
        D[pt*WS+c] = g_px[bn*64+c] - po;
    }
    __syncthreads();
    int r = t>>4, q = t&15;
    ull acc[4][2];
    {
        ull b0 = pack2(tb[q*4],   tb[q*4+1]);
        ull b1 = pack2(tb[q*4+2], tb[q*4+3]);
        #pragma unroll
        for (int i=0;i<4;i++){ acc[i][0]=b0; acc[i][1]=b1; }
    }
    GEMM_TW(acc, D, Wt)
    #pragma unroll
    for (int i=0;i<4;i++)
        #pragma unroll
        for (int jp=0;jp<2;jp++) {
            float2 f = unpack2(acc[i][jp]);
            int gi = (b*NN+n0+r*4+i)*64 + q*4 + 2*jp;
            g_po[gi]   = g_px[gi]   + fmaxf(f.x, 0.f);
            g_po[gi+1] = g_px[gi+1] + fmaxf(f.y, 0.f);
        }
}

// devoxelize(trilinear) * SE + point branch -> d_out
__global__ void k_out(float* __restrict__ out) {
    __shared__ int idxS[512];
    __shared__ float wS[512];
    __shared__ float obuf[4160];
    int blk = blockIdx.x;
    int b = blk>>6;
    int n0 = (blk&63)*64;
    int t = threadIdx.x;
    if (t < 64) {
        int n = n0 + t;
        const float* ncb = g_nc + b*3*NN;
        float f0=ncb[n], f1=ncb[NN+n], f2=ncb[2*NN+n];
        float fl0=floorf(f0), fl1=floorf(f1), fl2=floorf(f2);
        int x0=(int)fl0, y0=(int)fl1, z0=(int)fl2;
        float a0=f0-fl0, a1=f1-fl1, a2=f2-fl2;
        for (int k=0;k<8;k++){
            int dx=k>>2, dy=(k>>1)&1, dz=k&1;
            int xi=min(x0+dx,31), yi=min(y0+dy,31), zi=min(z0+dz,31);
            idxS[t*8+k] = (xi*32+yi)*32+zi;
            wS[t*8+k] = (dx?a0:1.f-a0)*(dy?a1:1.f-a1)*(dz?a2:1.f-a2);
        }
    }
    __syncthreads();
    int c = t&63, sub = t>>6;
    float sec = g_se[b*64+c];
    for (int nq=0; nq<16; nq++) {
        int nl = nq*4 + sub;
        float v = 0.f;
        #pragma unroll
        for (int k=0;k<8;k++)
            v += g_x[(b*VV + idxS[nl*8+k])*64 + c]*wS[nl*8+k];
        obuf[nl*65 + c] = v*sec + g_po[(b*NN+n0+nl)*64+c];
    }
    __syncthreads();
    for (int i=t; i<4096; i+=256) {
        int cc = i>>6, nl = i&63;
        out[(b*64+cc)*NN + n0+nl] = obuf[nl*65+cc];
    }
}

__global__ void k_copy(float* __restrict__ out, const float* __restrict__ coords) {
    int i = blockIdx.x*256 + threadIdx.x;
    if (i < BB*3*NN) out[BB*64*NN + i] = coords[i];
}

extern "C" void kernel_launch(void* const* d_in, const int* in_sizes, int n_in,
                              void* d_out, int out_size) {
    const float* feat   = (const float*)d_in[0];
    const float* coords = (const float*)d_in[1];
    const float* convw  = (const float*)d_in[2];
    const float* convb  = (const float*)d_in[3];
    const float* ln1g   = (const float*)d_in[4];
    const float* ln1b   = (const float*)d_in[5];
    const float* qkvw   = (const float*)d_in[6];
    const float* qkvb   = (const float*)d_in[7];
    const float* projw  = (const float*)d_in[8];
    const float* projb  = (const float*)d_in[9];
    const float* ln2g   = (const float*)d_in[10];
    const float* ln2b   = (const float*)d_in[11];
    const float* mw1    = (const float*)d_in[12];
    const float* mb1    = (const float*)d_in[13];
    const float* mw2    = (const float*)d_in[14];
    const float* mb2    = (const float*)d_in[15];
    const float* sew1   = (const float*)d_in[16];
    const float* sew2   = (const float*)d_in[17];
    const float* ptw    = (const float*)d_in[18];
    const float* ptb    = (const float*)d_in[19];
    const float* qw     = (const float*)d_in[20];
    const float* kw     = (const float*)d_in[21];
    const float* vw     = (const float*)d_in[22];
    const float* tw     = (const float*)d_in[23];
    const float* tb     = (const float*)d_in[24];
    float* out = (float*)d_out;

    cudaFuncSetAttribute(k_conv,    cudaFuncAttributeMaxDynamicSharedMemorySize, 77616);
    cudaFuncSetAttribute(k_winattn, cudaFuncAttributeMaxDynamicSharedMemorySize, 68096);
    cudaFuncSetAttribute(k_mlp,     cudaFuncAttributeMaxDynamicSharedMemorySize, 51200);

    k_initstats<<<8196, 256>>>(convw, coords);
    k_scatter<<<4096, 256>>>(feat);
    k_conv<<<1024, 256, 77616>>>(convb);
    k_winattn<<<2048, 256, 68096>>>(ln1g, ln1b, qkvw, qkvb, projw, projb); // launch #4 -> profiled
    k_mlp<<<2048, 256, 51200>>>(ln2g, ln2b, mw1, mb1, mw2, mb2);
    k_sereduce<<<128, 256>>>();
    k_se<<<1, 256>>>(sew1, sew2);
    k_pointmaps<<<256, 256>>>(feat, ptw, ptb, qw, kw, vw);
    k_pointattn<<<256, 256>>>();
    k_trans<<<256, 256>>>(tw, tb);
    k_out<<<256, 256>>>(out);
    if (out_size >= BB*64*NN + BB*3*NN)
        k_copy<<<192, 256>>>(out, coords);
}

// round 13
// speedup vs baseline: 1.0810x; 1.0014x over previous
#include <cuda_runtime.h>
#include <math.h>

#define BB 4
#define NN 4096
#define RR 32
#define VV (RR*RR*RR)

__device__ float g_grid[BB*VV*64];
__device__ float g_cnt[BB*VV];
__device__ float g_nc[BB*3*NN];
__device__ float g_x[BB*VV*64];
__device__ float g_wt[9*3*64*64];
__device__ float g_semean[BB*64];
__device__ float g_se[BB*64];
__device__ float g_px[BB*NN*64];
__device__ float g_pq[BB*NN*16];
__device__ float g_pk[BB*NN*16];
__device__ float g_pv[BB*NN*64];
__device__ float g_pop[4*BB*NN*64];
__device__ float g_po[BB*NN*64];
__device__ float g_pmx[4*BB*NN];
__device__ float g_pss[4*BB*NN];

typedef unsigned long long ull;

__device__ __forceinline__ ull pack2(float x, float y) {
    ull r; asm("mov.b64 %0, {%1, %2};" : "=l"(r) : "f"(x), "f"(y)); return r;
}
__device__ __forceinline__ float2 unpack2(ull v) {
    float2 f; asm("mov.b64 {%0, %1}, %2;" : "=f"(f.x), "=f"(f.y) : "l"(v)); return f;
}
__device__ __forceinline__ void fma2(ull &d, ull a, ull b) {
    asm("fma.rn.f32x2 %0, %1, %2, %0;" : "+l"(d) : "l"(a), "l"(b));
}
__device__ __forceinline__ void mul2(ull &d, ull a) {
    asm("mul.rn.f32x2 %0, %0, %1;" : "+l"(d) : "l"(a));
}

#define WS 66

// stage a 64x64 row-major weight matrix transposed into stride-68 smem
#define STAGE_W(WT, SRCROW) \
    for (int i_=threadIdx.x; i_<4096; i_+=256){ \
        int jj_=i_>>6, ci_=i_&63; \
        (WT)[ci_*68+jj_] = (SRCROW); \
    }

// GEMM microkernel over ci-pairs (round-12 best)
#define GEMM_TW(ACC, ABUF, WT) \
    for (int cp=0; cp<32; cp++) { \
        float4 we_ = *(const float4*)&(WT)[(2*cp)*68 + q*4]; \
        float4 wo_ = *(const float4*)&(WT)[(2*cp+1)*68 + q*4]; \
        ull we01_ = pack2(we_.x, we_.y), we23_ = pack2(we_.z, we_.w); \
        ull wo01_ = pack2(wo_.x, wo_.y), wo23_ = pack2(wo_.z, wo_.w); \
        _Pragma("unroll") \
        for (int i=0;i<4;i++) { \
            float2 a_ = *(const float2*)&(ABUF)[(r*4+i)*WS + 2*cp]; \
            ull ae_ = pack2(a_.x, a_.x); \
            ull ao_ = pack2(a_.y, a_.y); \
            fma2(ACC[i][0], ae_, we01_); \
            fma2(ACC[i][1], ae_, we23_); \
            fma2(ACC[i][0], ao_, wo01_); \
            fma2(ACC[i][1], ao_, wo23_); \
        } \
    }

// fused init (zero + conv weight transpose) + per-batch coord stats
__global__ void k_initstats(const float* __restrict__ w, const float* __restrict__ coords) {
    int blk = blockIdx.x;
    int t = threadIdx.x;
    if (blk < 8192) {
        int i = blk*256 + t;
        if (i < BB*VV*64/4) ((float4*)g_grid)[i] = make_float4(0.f,0.f,0.f,0.f);
        if (i < BB*VV)      g_cnt[i] = 0.f;
        if (i < BB*64)      g_semean[i] = 0.f;
        if (i < 9*3*64*64) {
            int co = i & 63;
            int ci = (i>>6) & 63;
            int kz = (i>>12) % 3;
            int g  = i / 12288;
            int dx = g/3, dy = g%3;
            g_wt[i] = w[(((co*64+ci)*3+dx)*3+dy)*3 + kz];
        }
        return;
    }
    int b = blk - 8192;
    __shared__ float red[256];
    __shared__ float mS[3], mxS;
    const float* cb = coords + b*3*NN;
    float s0=0.f, s1=0.f, s2=0.f;
    for (int n=t; n<NN; n+=256) { s0+=cb[n]; s1+=cb[NN+n]; s2+=cb[2*NN+n]; }
    float sv[3] = {s0,s1,s2};
    for (int d=0; d<3; d++) {
        red[t]=sv[d]; __syncthreads();
        for (int o=128;o;o>>=1){ if(t<o) red[t]+=red[t+o]; __syncthreads(); }
        if (t==0) mS[d] = red[0]*(1.f/NN);
        __syncthreads();
    }
    float m0=mS[0], m1=mS[1], m2=mS[2];
    float mx = 0.f;
    for (int n=t; n<NN; n+=256) {
        float dx=cb[n]-m0, dy=cb[NN+n]-m1, dz=cb[2*NN+n]-m2;
        mx = fmaxf(mx, dx*dx+dy*dy+dz*dz);
    }
    red[t]=mx; __syncthreads();
    for (int o=128;o;o>>=1){ if(t<o) red[t]=fmaxf(red[t],red[t+o]); __syncthreads(); }
    if (t==0) mxS = sqrtf(red[0]);
    __syncthreads();
    float inv = 1.f/(2.f*mxS);
    float* ncb = g_nc + b*3*NN;
    for (int n=t; n<NN; n+=256) {
        float v0 = ((cb[n]      -m0)*inv + 0.5f)*RR;
        float v1 = ((cb[NN+n]   -m1)*inv + 0.5f)*RR;
        float v2 = ((cb[2*NN+n] -m2)*inv + 0.5f)*RR;
        ncb[n]      = fminf(fmaxf(v0,0.f), 31.f);
        ncb[NN+n]   = fminf(fmaxf(v1,0.f), 31.f);
        ncb[2*NN+n] = fminf(fmaxf(v2,0.f), 31.f);
    }
}

__global__ void k_scatter(const float* __restrict__ feat) {
    int i = blockIdx.x*256 + threadIdx.x;
    const int PN = BB*NN;
    if (i >= 64*PN) return;
    int c = i / PN;
    int r = i % PN;
    int b = r / NN, n = r % NN;
    const float* ncb = g_nc + b*3*NN;
    int vx = (int)rintf(ncb[n]);
    int vy = (int)rintf(ncb[NN+n]);
    int vz = (int)rintf(ncb[2*NN+n]);
    int v = (vx*RR+vy)*RR+vz;
    if (c==0) atomicAdd(&g_cnt[b*VV+v], 1.f);
    atomicAdd(&g_grid[(b*VV+v)*64 + c], feat[(b*64+c)*NN + n]);
}

// 3x3x3 conv + bias + relu; ci-chunked sLine+sW => 51.5KB smem => 3 blocks/SM
__global__ void __launch_bounds__(256) k_conv(const float* __restrict__ bias) {
    extern __shared__ float sm[];
    float* sLine = sm;            // 6y * 34z * 32ci = 6528
    float* sW    = sm + 6528;     // 3kz * 32ci * 64co = 6144
    float* sCnt  = sm + 12672;    // 204
    int blk = blockIdx.x;
    int yg = blk & 7;
    int x  = (blk>>3) & 31;
    int b  = blk >> 8;
    int y0 = yg*4;
    int t  = threadIdx.x;
    int coq = t & 15;
    int yi  = (t >> 4) & 3;
    int zq  = t >> 6;
    ull acc[2][8];
    #pragma unroll
    for (int p=0; p<2; p++)
        #pragma unroll
        for (int z=0; z<8; z++) acc[p][z]=0ULL;

    for (int dx=0; dx<3; dx++) {
        __syncthreads();
        int xx = x + dx - 1;
        bool vx = (xx>=0 && xx<32);
        if (t < 204) {
            int yy = t/34, zz = t%34;
            int y = y0 - 1 + yy, z = zz - 1;
            float c = 1.f;
            if (vx && y>=0 && y<32 && z>=0 && z<32)
                c = fmaxf(g_cnt[b*VV + (xx*32+y)*32 + z], 1.f);
            sCnt[t] = __fdividef(1.f, c);
        }
        for (int ch=0; ch<2; ch++) {
            __syncthreads();   // sCnt ready / prior inner reads of sLine done
            for (int i=t; i<6528; i+=256) {
                int ci = i & 31;
                int zz = (i>>5) % 34;
                int yy = i / 1088;
                int y = y0 - 1 + yy, z = zz - 1;
                float val = 0.f;
                if (vx && y>=0 && y<32 && z>=0 && z<32)
                    val = g_grid[(b*VV + (xx*32+y)*32 + z)*64 + ch*32 + ci] * sCnt[yy*34+zz];
                sLine[i] = val;
            }
            for (int dy=0; dy<3; dy++) {
                const float* wsrc = g_wt + (dx*3+dy)*12288;
                __syncthreads();   // sLine ready (dy=0) / prior sW reads done
                for (int i=t; i<6144; i+=256) {
                    int kz = i / 2048;
                    int rem = i % 2048;
                    sW[i] = wsrc[kz*4096 + ch*2048 + rem];
                }
                __syncthreads();
                const float* Lb = sLine + (yi+dy)*1088 + zq*256;
                for (int cil=0; cil<32; cil++) {
                    const float* wb = sW + cil*64 + coq*4;
                    ull w0a = *(const ull*)(wb);
                    ull w0b = *(const ull*)(wb+2);
                    ull w1a = *(const ull*)(wb+2048);
                    ull w1b = *(const ull*)(wb+2050);
                    ull w2a = *(const ull*)(wb+4096);
                    ull w2b = *(const ull*)(wb+4098);
                    const float* L = Lb + cil;
                    float l0 = L[0], l1 = L[32];
                    ull p0 = pack2(l0,l0), p1 = pack2(l1,l1);
                    #pragma unroll
                    for (int z=0; z<8; z++) {
                        float l2 = L[(z+2)*32];
                        ull p2 = pack2(l2,l2);
                        fma2(acc[0][z], w0a, p0); fma2(acc[1][z], w0b, p0);
                        fma2(acc[0][z], w1a, p1); fma2(acc[1][z], w1b, p1);
                        fma2(acc[0][z], w2a, p2); fma2(acc[1][z], w2b, p2);
                        p0=p1; p1=p2;
                    }
                }
            }
        }
    }
    float b0 = bias[coq*4], b1 = bias[coq*4+1], b2 = bias[coq*4+2], b3 = bias[coq*4+3];
    int ybase = b*VV + (x*32 + y0 + yi)*32 + zq*8;
    #pragma unroll
    for (int z=0; z<8; z++) {
        float2 fa = unpack2(acc[0][z]);
        float2 fb = unpack2(acc[1][z]);
        float4 o;
        o.x = fmaxf(fa.x + b0, 0.f);
        o.y = fmaxf(fa.y + b1, 0.f);
        o.z = fmaxf(fb.x + b2, 0.f);
        o.w = fmaxf(fb.y + b3, 0.f);
        *(float4*)&g_x[(ybase+z)*64 + coq*4] = o;
    }
}

// window attention; Q stored into Hs (LN buffer) => 68KB => 3 blocks/SM
__global__ void k_winattn(const float* __restrict__ g1, const float* __restrict__ bb1,
                          const float* __restrict__ qkvw, const float* __restrict__ qkvb,
                          const float* __restrict__ pw, const float* __restrict__ pb) {
    extern __shared__ float sm[];
    float* Hs = sm;            // LN out -> Q -> attn out
    float* Ks = sm + 4224;
    float* Vs = sm + 8448;
    float* Wt = sm + 12672;    // 4352
    __shared__ int vmap[64];
    int blk = blockIdx.x;
    int b = blk >> 9;
    int rr = blk & 511;
    int wx = rr>>6, wy = (rr>>3)&7, wz = rr&7;
    int t = threadIdx.x;
    if (t < 64) {
        int ix = t>>4, iy = (t>>2)&3, iz = t&3;
        int v = ((wx*4+ix)*32 + (wy*4+iy))*32 + (wz*4+iz);
        vmap[t] = v;
        const float* row = g_x + (b*VV + v)*64;
        float mean=0.f, m2=0.f;
        for (int c=0;c<64;c++){ float xv=row[c]; mean+=xv; m2+=xv*xv; }
        mean *= 0.015625f;
        m2 = m2*0.015625f - mean*mean;
        float rs = rsqrtf(m2 + 1e-5f);
        for (int c=0;c<64;c++) Hs[t*WS+c] = (row[c]-mean)*rs*g1[c] + bb1[c];
    }
    int r = t>>4, q = t&15;
    // K then V (distinct dst buffers, Hs stays live)
    for (int cc=1; cc<3; cc++) {
        __syncthreads();
        STAGE_W(Wt, qkvw[(cc*64+jj_)*64+ci_])
        __syncthreads();
        ull acc[4][2];
        {
            ull b0 = pack2(qkvb[cc*64+q*4],   qkvb[cc*64+q*4+1]);
            ull b1 = pack2(qkvb[cc*64+q*4+2], qkvb[cc*64+q*4+3]);
            #pragma unroll
            for (int i=0;i<4;i++){ acc[i][0]=b0; acc[i][1]=b1; }
        }
        GEMM_TW(acc, Hs, Wt)
        float* dst = (cc==1)?Ks:Vs;
        #pragma unroll
        for (int i=0;i<4;i++)
            #pragma unroll
            for (int jp=0;jp<2;jp++) {
                float2 f = unpack2(acc[i][jp]);
                *(float2*)&dst[(r*4+i)*WS + q*4 + 2*jp] = f;
            }
    }
    // Q last: results in regs, sync, overwrite Hs
    __syncthreads();
    STAGE_W(Wt, qkvw[jj_*64+ci_])
    __syncthreads();
    {
        ull acc[4][2];
        ull b0 = pack2(qkvb[q*4],   qkvb[q*4+1]);
        ull b1 = pack2(qkvb[q*4+2], qkvb[q*4+3]);
        #pragma unroll
        for (int i=0;i<4;i++){ acc[i][0]=b0; acc[i][1]=b1; }
        GEMM_TW(acc, Hs, Wt)
        __syncthreads();   // all Hs reads complete before overwrite
        #pragma unroll
        for (int i=0;i<4;i++)
            #pragma unroll
            for (int jp=0;jp<2;jp++) {
                float2 f = unpack2(acc[i][jp]);
                *(float2*)&Hs[(r*4+i)*WS + q*4 + 2*jp] = f;
            }
    }
    __syncthreads();
    {   // attention: thread = (tok, head); q from Hs, out to same Hs cells
        int tok = t&63, h = t>>6;
        ull q2[8], o2[8];
        const ull* qrow = (const ull*)&Hs[tok*WS + h*16];
        #pragma unroll
        for (int k=0;k<8;k++){ q2[k]=qrow[k]; o2[k]=0ULL; }
        float mx = -3e30f, ss = 0.f;
        for (int m=0; m<64; m++) {
            const ull* kr = (const ull*)&Ks[m*WS + h*16];
            ull sp = 0ULL;
            #pragma unroll
            for (int k=0;k<8;k++) fma2(sp, q2[k], kr[k]);
            float2 sf = unpack2(sp);
            float s = (sf.x + sf.y)*0.25f;
            if (s > mx) {
                float cr = __expf(mx - s);
                ss *= cr;
                ull cp2 = pack2(cr,cr);
                #pragma unroll
                for (int k=0;k<8;k++) mul2(o2[k], cp2);
                mx = s;
            }
            float wv = __expf(s - mx);
            ss += wv;
            ull wp = pack2(wv,wv);
            const ull* vr = (const ull*)&Vs[m*WS + h*16];
            #pragma unroll
            for (int k=0;k<8;k++) fma2(o2[k], vr[k], wp);
        }
        float inv = 1.f/ss;
        #pragma unroll
        for (int k=0;k<8;k++) {
            float2 f = unpack2(o2[k]);
            Hs[tok*WS + h*16 + 2*k]   = f.x*inv;
            Hs[tok*WS + h*16 + 2*k+1] = f.y*inv;
        }
    }
    __syncthreads();
    STAGE_W(Wt, pw[jj_*64+ci_])
    __syncthreads();
    {
        ull acc[4][2];
        ull b0 = pack2(pb[q*4],   pb[q*4+1]);
        ull b1 = pack2(pb[q*4+2], pb[q*4+3]);
        #pragma unroll
        for (int i=0;i<4;i++){ acc[i][0]=b0; acc[i][1]=b1; }
        GEMM_TW(acc, Hs, Wt)
        #pragma unroll
        for (int i=0;i<4;i++)
            #pragma unroll
            for (int jp=0;jp<2;jp++) {
                float2 f = unpack2(acc[i][jp]);
                int gi = (b*VV + vmap[r*4+i])*64 + q*4 + 2*jp;
                g_x[gi]   += f.x;
                g_x[gi+1] += f.y;
            }
    }
}

// LN2 + MLP(gelu-tanh via exp) + residual; 64 tokens / block
__global__ void k_mlp(const float* __restrict__ g2, const float* __restrict__ b2g,
                      const float* __restrict__ w1, const float* __restrict__ mb1,
                      const float* __restrict__ w2, const float* __restrict__ mb2) {
    extern __shared__ float sm[];
    float* Aa = sm;            // stride 66
    float* Hc = sm + 4224;     // stride 66
    float* Wt = sm + 8448;     // 4352
    int t = threadIdx.x;
    int gt0 = blockIdx.x*64;
    if (t < 64) {
        const float* row = g_x + (gt0+t)*64;
        float mean=0.f, m2=0.f;
        for (int c=0;c<64;c++){ float xv=row[c]; mean+=xv; m2+=xv*xv; }
        mean *= 0.015625f;
        m2 = m2*0.015625f - mean*mean;
        float rs = rsqrtf(m2 + 1e-5f);
        for (int c=0;c<64;c++) Aa[t*WS+c] = (row[c]-mean)*rs*g2[c] + b2g[c];
    }
    int r = t>>4, q = t&15;
    ull o2[4][2];
    {
        ull b0 = pack2(mb2[q*4],   mb2[q*4+1]);
        ull b1 = pack2(mb2[q*4+2], mb2[q*4+3]);
        #pragma unroll
        for (int i=0;i<4;i++){ o2[i][0]=b0; o2[i][1]=b1; }
    }
    for (int ch=0; ch<4; ch++) {
        __syncthreads();
        STAGE_W(Wt, w1[(ch*64+jj_)*64+ci_])
        __syncthreads();
        ull h2[4][2];
        {
            ull b0 = pack2(mb1[ch*64+q*4],   mb1[ch*64+q*4+1]);
            ull b1 = pack2(mb1[ch*64+q*4+2], mb1[ch*64+q*4+3]);
            #pragma unroll
            for (int i=0;i<4;i++){ h2[i][0]=b0; h2[i][1]=b1; }
        }
        GEMM_TW(h2, Aa, Wt)
        __syncthreads();
        #pragma unroll
        for (int i=0;i<4;i++)
            #pragma unroll
            for (int jp=0;jp<2;jp++) {
                float2 f = unpack2(h2[i][jp]);
                float u0 = 1.5957691216f*(f.x + 0.044715f*f.x*f.x*f.x);
                float u1 = 1.5957691216f*(f.y + 0.044715f*f.y*f.y*f.y);
                float t0 = 1.f - __fdividef(2.f, 1.f + __expf(u0));
                float t1 = 1.f - __fdividef(2.f, 1.f + __expf(u1));
                float2 g;
                g.x = 0.5f*f.x*(1.f + t0);
                g.y = 0.5f*f.y*(1.f + t1);
                *(float2*)&Hc[(r*4+i)*WS + q*4 + 2*jp] = g;
            }
        __syncthreads();
        STAGE_W(Wt, w2[jj_*256 + ch*64 + ci_])
        __syncthreads();
        GEMM_TW(o2, Hc, Wt)
    }
    #pragma unroll
    for (int i=0;i<4;i++)
        #pragma unroll
        for (int jp=0;jp<2;jp++) {
            float2 f = unpack2(o2[i][jp]);
            int gi = (gt0 + r*4+i)*64 + q*4 + 2*jp;
            g_x[gi]   += f.x;
            g_x[gi+1] += f.y;
        }
}

__global__ void k_sereduce() {
    int blk = blockIdx.x;
    int b = blk>>5, chunk = blk&31;
    int t = threadIdx.x;
    const float* base = g_x + (b*VV + chunk*1024)*64;
    float s = 0.f;
    for (int i=t; i<65536; i+=256) s += base[i];
    __shared__ float red[256];
    red[t]=s; __syncthreads();
    if (t < 64) {
        float v = red[t]+red[t+64]+red[t+128]+red[t+192];
        atomicAdd(&g_semean[b*64 + t], v);
    }
}

__global__ void k_se(const float* __restrict__ w1, const float* __restrict__ w2) {
    int t = threadIdx.x;
    int b = t>>6, c = t&63;
    __shared__ float hid[4][8];
    if (c < 8) {
        float a = 0.f;
        for (int ci=0;ci<64;ci++) a += w1[c*64+ci]*g_semean[b*64+ci];
        a *= (1.f/VV);
        hid[b][c] = fmaxf(a, 0.f);
    }
    __syncthreads();
    float s = 0.f;
    for (int j=0;j<8;j++) s += w2[c*8+j]*hid[b][j];
    g_se[b*64+c] = 1.f/(1.f + __expf(-s));
}

__global__ void k_pointmaps(const float* __restrict__ feat, const float* __restrict__ pw,
                            const float* __restrict__ pb, const float* __restrict__ qw,
                            const float* __restrict__ kw, const float* __restrict__ vw) {
    __shared__ float F[4224];     // stride 66
    __shared__ float Wt[4352];
    int blk = blockIdx.x;
    int b = blk>>6;
    int n0 = (blk&63)*64;
    int t = threadIdx.x;
    for (int i=t; i<4096; i+=256){ int pt=i&63, ci=i>>6; F[pt*WS+ci] = feat[(b*64+ci)*NN + n0+pt]; }
    STAGE_W(Wt, pw[jj_*64+ci_])
    __syncthreads();
    int r = t>>4, q = t&15;
    {
        ull acc[4][2];
        ull b0 = pack2(pb[q*4],   pb[q*4+1]);
        ull b1 = pack2(pb[q*4+2], pb[q*4+3]);
        #pragma unroll
        for (int i=0;i<4;i++){ acc[i][0]=b0; acc[i][1]=b1; }
        GEMM_TW(acc, F, Wt)
        __syncthreads();
        #pragma unroll
        for (int i=0;i<4;i++)
            #pragma unroll
            for (int jp=0;jp<2;jp++) {
                float2 f = unpack2(acc[i][jp]);
                f.x = fmaxf(f.x, 0.f);
                f.y = fmaxf(f.y, 0.f);
                *(float2*)&F[(r*4+i)*WS + q*4 + 2*jp] = f;
                *(float2*)&g_px[(b*NN + n0 + r*4+i)*64 + q*4 + 2*jp] = f;
            }
    }
    __syncthreads();
    for (int i=t; i<1024; i+=256) Wt[i] = qw[i];
    for (int i=t; i<1024; i+=256) Wt[1024+i] = kw[i];
    __syncthreads();
    {
        int pt = t&63, dh = t>>6;
        for (int dl=0; dl<4; dl++) {
            int d = dh*4 + dl;
            float aq=0.f, ak=0.f;
            for (int ci=0; ci<64; ci++) {
                float xv = F[pt*WS+ci];
                aq += xv*Wt[d*64+ci];
                ak += xv*Wt[1024 + d*64+ci];
            }
            g_pq[(b*NN+n0+pt)*16 + d] = aq;
            g_pk[(b*NN+n0+pt)*16 + d] = ak;
        }
    }
    __syncthreads();
    STAGE_W(Wt, vw[jj_*64+ci_])
    __syncthreads();
    {
        ull acc[4][2];
        #pragma unroll
        for (int i=0;i<4;i++){ acc[i][0]=0ULL; acc[i][1]=0ULL; }
        GEMM_TW(acc, F, Wt)
        #pragma unroll
        for (int i=0;i<4;i++)
            #pragma unroll
            for (int jp=0;jp<2;jp++) {
                float2 f = unpack2(acc[i][jp]);
                *(float2*)&g_pv[(b*NN + n0 + r*4+i)*64 + q*4 + 2*jp] = f;
            }
    }
}

// flash-style point attention, key-split into 4 segments of 1024
__global__ void k_pointattn() {
    __shared__ __align__(16) float Ks[2048];
    __shared__ __align__(16) float Vs[8192];
    int blk = blockIdx.x;
    int b = blk >> 6;
    int rem = blk & 63;
    int qg = rem >> 2;
    int seg = rem & 3;
    int t = threadIdx.x;
    int n = qg*256 + t;
    int bn = b*NN + n;
    ull q2[8];
    {
        const ull* qp = (const ull*)&g_pq[bn*16];
        #pragma unroll
        for (int k=0;k<8;k++) q2[k] = qp[k];
    }
    ull o2[32];
    #pragma unroll
    for (int k=0;k<32;k++) o2[k]=0ULL;
    float mx=-3e30f, ss=0.f;
    int m0base = seg*1024;
    for (int tile=0; tile<8; tile++) {
        int m0 = m0base + tile*128;
        __syncthreads();
        const float4* ksrc = (const float4*)&g_pk[(b*NN+m0)*16];
        float4* kdst = (float4*)Ks;
        for (int i=t; i<512; i+=256) kdst[i] = ksrc[i];
        const float4* vsrc = (const float4*)&g_pv[(b*NN+m0)*64];
        float4* vdst = (float4*)Vs;
        for (int i=t; i<2048; i+=256) vdst[i] = vsrc[i];
        __syncthreads();
        for (int mm=0; mm<128; mm++) {
            const ull* kr = (const ull*)&Ks[mm*16];
            ull sp = 0ULL;
            #pragma unroll
            for (int k=0;k<8;k++) fma2(sp, q2[k], kr[k]);
            float2 sf = unpack2(sp);
            float s = (sf.x + sf.y)*0.25f;
            if (s > mx) {
                float cr = __expf(mx - s);
                ss *= cr;
                ull cp = pack2(cr, cr);
                #pragma unroll
                for (int k=0;k<32;k++) mul2(o2[k], cp);
                mx = s;
            }
            float w = __expf(s - mx);
            ss += w;
            ull wp = pack2(w, w);
            const ulonglong2* vr = (const ulonglong2*)&Vs[mm*64];
            #pragma unroll
            for (int k=0;k<16;k++) {
                ulonglong2 vv = vr[k];
                fma2(o2[2*k],   vv.x, wp);
                fma2(o2[2*k+1], vv.y, wp);
            }
        }
    }
    g_pmx[seg*(BB*NN) + bn] = mx;
    g_pss[seg*(BB*NN) + bn] = ss;
    float inv = 1.f/ss;
    float2* dst = (float2*)&g_pop[(size_t)seg*BB*NN*64 + (size_t)bn*64];
    #pragma unroll
    for (int k=0;k<32;k++) {
        float2 f = unpack2(o2[k]);
        f.x *= inv; f.y *= inv;
        dst[k] = f;
    }
}

// merge 4 attn segments; off = relu(tw@(px-po)+tb); g_po := px + off
__global__ void k_trans(const float* __restrict__ tw, const float* __restrict__ tb) {
    __shared__ float D[4224];     // stride 66
    __shared__ float Wt[4352];
    __shared__ float Aw[320];
    int blk = blockIdx.x;
    int b = blk>>6;
    int n0 = (blk&63)*64;
    int t = threadIdx.x;
    if (t < 64) {
        int bn = b*NN + n0 + t;
        float m[4], s[4];
        float mm = -3e30f;
        #pragma unroll
        for (int sg=0; sg<4; sg++) {
            m[sg] = g_pmx[sg*(BB*NN)+bn];
            s[sg] = g_pss[sg*(BB*NN)+bn];
            mm = fmaxf(mm, m[sg]);
        }
        float den = 0.f;
        #pragma unroll
        for (int sg=0; sg<4; sg++) {
            float a = s[sg]*__expf(m[sg]-mm);
            Aw[t*5+sg] = a;
            den += a;
        }
        Aw[t*5+4] = 1.f/den;
    }
    STAGE_W(Wt, tw[jj_*64+ci_])
    __syncthreads();
    for (int i=t; i<4096; i+=256){
        int pt=i>>6, c=i&63;
        int bn = b*NN + n0 + pt;
        float po = 0.f;
        #pragma unroll
        for (int sg=0; sg<4; sg++)
            po += g_pop[(size_t)sg*BB*NN*64 + (size_t)bn*64 + c]*Aw[pt*5+sg];
        po *= Aw[pt*5+4];
        D[pt*WS+c] = g_px[bn*64+c] - po;
    }
    __syncthreads();
    int r = t>>4, q = t&15;
    ull acc[4][2];
    {
        ull b0 = pack2(tb[q*4],   tb[q*4+1]);
        ull b1 = pack2(tb[q*4+2], tb[q*4+3]);
        #pragma unroll
        for (int i=0;i<4;i++){ acc[i][0]=b0; acc[i][1]=b1; }
    }
    GEMM_TW(acc, D, Wt)
    #pragma unroll
    for (int i=0;i<4;i++)
        #pragma unroll
        for (int jp=0;jp<2;jp++) {
            float2 f = unpack2(acc[i][jp]);
            int gi = (b*NN+n0+r*4+i)*64 + q*4 + 2*jp;
            g_po[gi]   = g_px[gi]   + fmaxf(f.x, 0.f);
            g_po[gi+1] = g_px[gi+1] + fmaxf(f.y, 0.f);
        }
}

// devoxelize(trilinear) * SE + point branch -> d_out
__global__ void k_out(float* __restrict__ out) {
    __shared__ int idxS[512];
    __shared__ float wS[512];
    __shared__ float obuf[4160];
    int blk = blockIdx.x;
    int b = blk>>6;
    int n0 = (blk&63)*64;
    int t = threadIdx.x;
    if (t < 64) {
        int n = n0 + t;
        const float* ncb = g_nc + b*3*NN;
        float f0=ncb[n], f1=ncb[NN+n], f2=ncb[2*NN+n];
        float fl0=floorf(f0), fl1=floorf(f1), fl2=floorf(f2);
        int x0=(int)fl0, y0=(int)fl1, z0=(int)fl2;
        float a0=f0-fl0, a1=f1-fl1, a2=f2-fl2;
        for (int k=0;k<8;k++){
            int dx=k>>2, dy=(k>>1)&1, dz=k&1;
            int xi=min(x0+dx,31), yi=min(y0+dy,31), zi=min(z0+dz,31);
            idxS[t*8+k] = (xi*32+yi)*32+zi;
            wS[t*8+k] = (dx?a0:1.f-a0)*(dy?a1:1.f-a1)*(dz?a2:1.f-a2);
        }
    }
    __syncthreads();
    int c = t&63, sub = t>>6;
    float sec = g_se[b*64+c];
    for (int nq=0; nq<16; nq++) {
        int nl = nq*4 + sub;
        float v = 0.f;
        #pragma unroll
        for (int k=0;k<8;k++)
            v += g_x[(b*VV + idxS[nl*8+k])*64 + c]*wS[nl*8+k];
        obuf[nl*65 + c] = v*sec + g_po[(b*NN+n0+nl)*64+c];
    }
    __syncthreads();
    for (int i=t; i<4096; i+=256) {
        int cc = i>>6, nl = i&63;
        out[(b*64+cc)*NN + n0+nl] = obuf[nl*65+cc];
    }
}

__global__ void k_copy(float* __restrict__ out, const float* __restrict__ coords) {
    int i = blockIdx.x*256 + threadIdx.x;
    if (i < BB*3*NN) out[BB*64*NN + i] = coords[i];
}

extern "C" void kernel_launch(void* const* d_in, const int* in_sizes, int n_in,
                              void* d_out, int out_size) {
    const float* feat   = (const float*)d_in[0];
    const float* coords = (const float*)d_in[1];
    const float* convw  = (const float*)d_in[2];
    const float* convb  = (const float*)d_in[3];
    const float* ln1g   = (const float*)d_in[4];
    const float* ln1b   = (const float*)d_in[5];
    const float* qkvw   = (const float*)d_in[6];
    const float* qkvb   = (const float*)d_in[7];
    const float* projw  = (const float*)d_in[8];
    const float* projb  = (const float*)d_in[9];
    const float* ln2g   = (const float*)d_in[10];
    const float* ln2b   = (const float*)d_in[11];
    const float* mw1    = (const float*)d_in[12];
    const float* mb1    = (const float*)d_in[13];
    const float* mw2    = (const float*)d_in[14];
    const float* mb2    = (const float*)d_in[15];
    const float* sew1   = (const float*)d_in[16];
    const float* sew2   = (const float*)d_in[17];
    const float* ptw    = (const float*)d_in[18];
    const float* ptb    = (const float*)d_in[19];
    const float* qw     = (const float*)d_in[20];
    const float* kw     = (const float*)d_in[21];
    const float* vw     = (const float*)d_in[22];
    const float* tw     = (const float*)d_in[23];
    const float* tb     = (const float*)d_in[24];
    float* out = (float*)d_out;

    cudaFuncSetAttribute(k_conv,    cudaFuncAttributeMaxDynamicSharedMemorySize, 51504);
    cudaFuncSetAttribute(k_winattn, cudaFuncAttributeMaxDynamicSharedMemorySize, 68096);
    cudaFuncSetAttribute(k_mlp,     cudaFuncAttributeMaxDynamicSharedMemorySize, 51200);

    if (out_size >= BB*64*NN + BB*3*NN)
        k_copy<<<192, 256>>>(out, coords);            // launch #1 (independent)
    k_initstats<<<8196, 256>>>(convw, coords);        // #2
    k_scatter<<<4096, 256>>>(feat);                   // #3
    k_conv<<<1024, 256, 51504>>>(convb);              // #4 -> profiled
    k_winattn<<<2048, 256, 68096>>>(ln1g, ln1b, qkvw, qkvb, projw, projb);
    k_mlp<<<2048, 256, 51200>>>(ln2g, ln2b, mw1, mb1, mw2, mb2);
    k_sereduce<<<128, 256>>>();
    k_se<<<1, 256>>>(sew1, sew2);
    k_pointmaps<<<256, 256>>>(feat, ptw, ptb, qw, kw, vw);
    k_pointattn<<<256, 256>>>();
    k_trans<<<256, 256>>>(tw, tb);
    k_out<<<256, 256>>>(out);
}